// round 9
// baseline (speedup 1.0000x reference)
#include <cuda_runtime.h>
#include <cuda_bf16.h>
#include <cstdint>

#define N_NODES 100000
#define N_EDGES 600000
#define N_GRAPHS 64
#define BN_EPS 1e-5f
#define SCAN_BS 256
#define NB_SCAN ((N_NODES + SCAN_BS - 1) / SCAN_BS)   // 391
#define EB ((N_EDGES + 255) / 256)                     // 2344
#define WTOT 30720
#define WB ((WTOT + 255) / 256)                        // 120

// ================= helpers =================
__device__ __forceinline__ uint32_t smem_u32(const void* p) {
    uint32_t a;
    asm("{ .reg .u64 t; cvta.to.shared.u64 t, %1; cvt.u32.u64 %0, t; }" : "=r"(a) : "l"(p));
    return a;
}
__device__ __forceinline__ void sts32(uint32_t addr, uint32_t v) {
    asm volatile("st.shared.b32 [%0], %1;" :: "r"(addr), "r"(v));
}
__device__ __forceinline__ void ldsm4(uint32_t r[4], uint32_t a) {
    asm volatile("ldmatrix.sync.aligned.m8n8.x4.shared.b16 {%0,%1,%2,%3}, [%4];"
                 : "=r"(r[0]), "=r"(r[1]), "=r"(r[2]), "=r"(r[3]) : "r"(a));
}
__device__ __forceinline__ void ldsm2(uint32_t r[2], uint32_t a) {
    asm volatile("ldmatrix.sync.aligned.m8n8.x2.shared.b16 {%0,%1}, [%2];"
                 : "=r"(r[0]), "=r"(r[1]) : "r"(a));
}
__device__ __forceinline__ void mma_bf16(float c[4], const uint32_t a[4], const uint32_t b[2]) {
    asm volatile("mma.sync.aligned.m16n8k16.row.col.f32.bf16.bf16.f32 "
                 "{%0,%1,%2,%3}, {%4,%5,%6,%7}, {%8,%9}, {%0,%1,%2,%3};"
                 : "+f"(c[0]), "+f"(c[1]), "+f"(c[2]), "+f"(c[3])
                 : "r"(a[0]), "r"(a[1]), "r"(a[2]), "r"(a[3]), "r"(b[0]), "r"(b[1]));
}
__device__ __forceinline__ void split2(float a, float b, uint32_t& hi, uint32_t& lo) {
    __nv_bfloat16 ha = __float2bfloat16(a), hb = __float2bfloat16(b);
    __nv_bfloat16 la = __float2bfloat16(a - __bfloat162float(ha));
    __nv_bfloat16 lb = __float2bfloat16(b - __bfloat162float(hb));
    __nv_bfloat162 H; H.x = ha; H.y = hb;
    __nv_bfloat162 L; L.x = la; L.y = lb;
    hi = *(uint32_t*)&H; lo = *(uint32_t*)&L;
}

// ================= scratch =================
__device__ float g_y[(size_t)N_NODES * 64];
__device__ __nv_bfloat16 g_aghi[(size_t)N_NODES * 64];
__device__ __nv_bfloat16 g_aglo[(size_t)N_NODES * 64];
__device__ float g_sums[N_GRAPHS * 96];
__device__ int   g_cnts[N_GRAPHS];
__device__ int   g_src[N_EDGES];
__device__ int   g_dst[N_EDGES];
__device__ int   g_batch32[N_NODES];
__device__ int   g_deg[N_NODES];
__device__ int   g_rowptr[N_NODES + 1];
__device__ int   g_cursor[N_NODES];
__device__ int   g_col[N_EDGES];
__device__ int   g_part[NB_SCAN];
__device__ int   g_poff[NB_SCAN];
__device__ int   g_flags[2];
__device__ __nv_bfloat16 g_whi[WTOT];
__device__ __nv_bfloat16 g_wlo[WTOT];

// ================= mega-prep: detect dtypes + zero deg/sums/cnts + weight split =================
__global__ void prep_kernel(const void* ei, const void* batch, int* flags,
                            int* __restrict__ deg, float* __restrict__ sums,
                            int* __restrict__ cnts,
                            const float* w10, const float* w20, const float* w11,
                            const float* w21, const float* w12, const float* w22,
                            __nv_bfloat16* __restrict__ whi, __nv_bfloat16* __restrict__ wlo) {
    int b = blockIdx.x, t = threadIdx.x;
    if (b < NB_SCAN) {
        int i = b * 256 + t;
        if (i < N_NODES) deg[i] = 0;
    } else if (b == NB_SCAN || b == NB_SCAN + 1) {
        __shared__ int ok;
        if (t == 0) ok = 1;
        __syncthreads();
        int which = b - NB_SCAN;
        const void* p = (which == 0) ? ei : batch;
        long long n64_max = (which == 0) ? (long long)N_EDGES : (long long)N_NODES / 2;
        int maxval = (which == 0) ? N_NODES : N_GRAPHS;
        long long idx = (long long)t * (n64_max - 1) / 255;
        long long v = ((const long long*)p)[idx];
        if (v < 0 || v >= maxval) atomicAnd(&ok, 0);
        __syncthreads();
        if (t == 0) flags[which] = ok;
    } else if (b == NB_SCAN + 2) {
        for (int i = t; i < N_GRAPHS * 96; i += 256) sums[i] = 0.f;
        if (t < N_GRAPHS) cnts[t] = 0;
    } else {
        int i = (b - (NB_SCAN + 3)) * 256 + t;
        if (i >= WTOT) return;
        const float* src; int K, off;
        if      (i < 8192)  { src = w10; K = 128; off = 0; }
        else if (i < 12288) { src = w20; K = 64;  off = 8192; }
        else if (i < 16384) { src = w11; K = 64;  off = 12288; }
        else if (i < 20480) { src = w21; K = 64;  off = 16384; }
        else if (i < 24576) { src = w12; K = 64;  off = 20480; }
        else                { src = w22; K = 64;  off = 24576; }
        int N = (i < 24576) ? 64 : 96;
        int local = i - off;
        int n = local / K, k = local % K;
        float v = src[k * N + n];
        __nv_bfloat16 h = __float2bfloat16(v);
        whi[i] = h;
        wlo[i] = __float2bfloat16(v - __bfloat162float(h));
    }
}

// ================= convert edges + batch (one grid); also counts nodes/graph =================
__global__ void convert_all_kernel(const void* ei, const void* batch, const int* flags,
                                   int* __restrict__ src, int* __restrict__ dst,
                                   int* __restrict__ deg, int* __restrict__ b32,
                                   int* __restrict__ cnts) {
    int b = blockIdx.x, t = threadIdx.x;
    if (b < EB) {
        int i = b * 256 + t;
        if (i >= N_EDGES) return;
        int s, d;
        if (flags[0]) {
            const long long* p = (const long long*)ei;
            s = (int)p[i]; d = (int)p[N_EDGES + i];
        } else {
            const int* p = (const int*)ei;
            s = p[i]; d = p[N_EDGES + i];
        }
        src[i] = s; dst[i] = d;
        atomicAdd(&deg[d], 1);
    } else {
        int i = (b - EB) * 256 + t;
        if (i >= N_NODES) return;
        int v;
        if (flags[1]) v = (int)((const long long*)batch)[i];
        else          v = ((const int*)batch)[i];
        b32[i] = v;
        atomicAdd(&cnts[v], 1);   // warp-aggregated (sorted batch -> uniform addr)
    }
}

// ================= scan chain =================
__global__ void partials_kernel(const int* __restrict__ deg, int* __restrict__ part) {
    __shared__ int sm[SCAN_BS];
    int i = blockIdx.x * SCAN_BS + threadIdx.x;
    sm[threadIdx.x] = (i < N_NODES) ? deg[i] : 0;
    __syncthreads();
#pragma unroll
    for (int s = SCAN_BS / 2; s > 0; s >>= 1) {
        if (threadIdx.x < s) sm[threadIdx.x] += sm[threadIdx.x + s];
        __syncthreads();
    }
    if (threadIdx.x == 0) part[blockIdx.x] = sm[0];
}
// parallel exclusive scan of 391 block sums (512 threads, Hillis-Steele)
__global__ void scan_partials_kernel(const int* __restrict__ part, int* __restrict__ poff) {
    __shared__ int sm[512];
    int t = threadIdx.x;
    int v = (t < NB_SCAN) ? part[t] : 0;
    sm[t] = v;
    __syncthreads();
#pragma unroll
    for (int off = 1; off < 512; off <<= 1) {
        int x = (t >= off) ? sm[t - off] : 0;
        __syncthreads();
        sm[t] += x;
        __syncthreads();
    }
    if (t < NB_SCAN) poff[t] = sm[t] - v;
}
__global__ void rowptr_kernel(const int* __restrict__ deg, const int* __restrict__ poff,
                              int* __restrict__ rowptr, int* __restrict__ cursor) {
    __shared__ int sm[SCAN_BS];
    int b = blockIdx.x, t = threadIdx.x;
    int i = b * SCAN_BS + t;
    int v = (i < N_NODES) ? deg[i] : 0;
    sm[t] = v;
    __syncthreads();
    for (int off = 1; off < SCAN_BS; off <<= 1) {
        int x = (t >= off) ? sm[t - off] : 0;
        __syncthreads();
        sm[t] += x;
        __syncthreads();
    }
    if (i < N_NODES) {
        int r = poff[b] + sm[t] - v;
        rowptr[i] = r;
        cursor[i] = r;
    }
    if (i == N_NODES - 1) rowptr[N_NODES] = poff[b] + sm[t];
}
__global__ void fill_kernel(const int* __restrict__ src, const int* __restrict__ dst,
                            int* __restrict__ cursor, int* __restrict__ col) {
    int e = blockIdx.x * blockDim.x + threadIdx.x;
    if (e >= N_EDGES) return;
    int d = dst[e];
    int pos = atomicAdd(&cursor[d], 1);
    col[pos] = src[e];
}

// ================= standalone GEMM layer0: Y = X @ W1 (K=128, N=64), fp32 out =================
__global__ __launch_bounds__(128) void hgemm_l0(const float* __restrict__ X,
                                                const __nv_bfloat16* __restrict__ Whi,
                                                const __nv_bfloat16* __restrict__ Wlo,
                                                float* __restrict__ Y) {
    constexpr int K = 128, N = 64;
    constexpr int SP = K + 8, SPB = SP * 2, NT = N / 8;
    extern __shared__ char dsm[];
    uint32_t aHi = smem_u32(dsm);
    uint32_t aLo = aHi + 128 * SPB;
    uint32_t wHi = aLo + 128 * SPB;
    uint32_t wLo = wHi + N * SPB;

    const int tid = threadIdx.x, warp = tid >> 5, lane = tid & 31;
    const int base = blockIdx.x * 128;

    for (int i = tid; i < N * K / 2; i += 128) {
        int byte = i * 4;
        int row = byte / (K * 2), kb = byte - row * (K * 2);
        uint32_t off = (uint32_t)row * SPB + kb;
        sts32(wHi + off, ((const uint32_t*)Whi)[i]);
        sts32(wLo + off, ((const uint32_t*)Wlo)[i]);
    }
    constexpr int N4 = K / 4;
    for (int i = tid; i < 128 * N4; i += 128) {
        int row = i / N4, c4 = i - row * N4, col = c4 * 4;
        float4 v = make_float4(0.f, 0.f, 0.f, 0.f);
        if (base + row < N_NODES) v = ((const float4*)X)[(size_t)(base + row) * N4 + c4];
        uint32_t h01, l01, h23, l23;
        split2(v.x, v.y, h01, l01);
        split2(v.z, v.w, h23, l23);
        uint32_t off = (uint32_t)row * SPB + col * 2;
        sts32(aHi + off, h01); sts32(aHi + off + 4, h23);
        sts32(aLo + off, l01); sts32(aLo + off + 4, l23);
    }
    __syncthreads();

    float acc[2][NT][4];
#pragma unroll
    for (int t = 0; t < 2; t++)
#pragma unroll
        for (int n = 0; n < NT; n++)
#pragma unroll
            for (int j = 0; j < 4; j++) acc[t][n][j] = 0.f;

    const int arow = warp * 32 + (lane & 15);
    const int ahalf = lane >> 4;
    const int brow = lane & 7;
    const int bhalf = (lane >> 3) & 1;

#pragma unroll
    for (int s = 0; s < 3; s++) {
        uint32_t Ab = (s == 2) ? aLo : aHi;
        uint32_t Wb = (s == 1) ? wLo : wHi;
#pragma unroll
        for (int k16 = 0; k16 < K / 16; k16++) {
            uint32_t kbyte = (uint32_t)(k16 * 16) * 2;
            uint32_t af0[4], af1[4];
            ldsm4(af0, Ab + (uint32_t)arow * SPB + kbyte + ahalf * 16);
            ldsm4(af1, Ab + (uint32_t)(arow + 16) * SPB + kbyte + ahalf * 16);
#pragma unroll
            for (int n8 = 0; n8 < NT; n8++) {
                uint32_t bf[2];
                ldsm2(bf, Wb + (uint32_t)(n8 * 8 + brow) * SPB + kbyte + bhalf * 16);
                mma_bf16(acc[0][n8], af0, bf);
                mma_bf16(acc[1][n8], af1, bf);
            }
        }
    }
    const int r_in_warp = lane >> 2;
    const int cpair = (lane & 3) * 2;
#pragma unroll
    for (int t = 0; t < 2; t++) {
        int row0 = base + warp * 32 + t * 16 + r_in_warp;
        int row1 = row0 + 8;
#pragma unroll
        for (int n8 = 0; n8 < NT; n8++) {
            int col = n8 * 8 + cpair;
            if (row0 < N_NODES) *(float2*)(Y + (size_t)row0 * N + col) = make_float2(acc[t][n8][0], acc[t][n8][1]);
            if (row1 < N_NODES) *(float2*)(Y + (size_t)row1 * N + col) = make_float2(acc[t][n8][2], acc[t][n8][3]);
        }
    }
}

// ================= gather: AG = split(ReLU(gathersum + b1)) as bf16 hi/lo =================
__global__ __launch_bounds__(256) void gather_kernel(const float* __restrict__ Y,
                                                     const int* __restrict__ rowptr,
                                                     const int* __restrict__ col,
                                                     const float* __restrict__ b1,
                                                     __nv_bfloat16* __restrict__ AGhi,
                                                     __nv_bfloat16* __restrict__ AGlo) {
    int w = (blockIdx.x * blockDim.x + threadIdx.x) >> 5;
    int lane = threadIdx.x & 31;
    if (w >= N_NODES) return;
    const float2* y2 = (const float2*)Y;
    float2 bias = ((const float2*)b1)[lane];
    int r0 = rowptr[w], r1 = rowptr[w + 1];
    float2 acc = y2[(size_t)w * 32 + lane];
    int e = r0;
    for (; e + 3 < r1; e += 4) {
        int s0 = col[e], s1 = col[e + 1], s2 = col[e + 2], s3 = col[e + 3];
        float2 a = y2[(size_t)s0 * 32 + lane];
        float2 b = y2[(size_t)s1 * 32 + lane];
        float2 c = y2[(size_t)s2 * 32 + lane];
        float2 d = y2[(size_t)s3 * 32 + lane];
        acc.x += (a.x + b.x) + (c.x + d.x);
        acc.y += (a.y + b.y) + (c.y + d.y);
    }
    if (e + 1 < r1) {
        int s0 = col[e], s1 = col[e + 1];
        float2 a = y2[(size_t)s0 * 32 + lane];
        float2 b = y2[(size_t)s1 * 32 + lane];
        acc.x += a.x + b.x;
        acc.y += a.y + b.y;
        e += 2;
    }
    if (e < r1) {
        int s = col[e];
        float2 a = y2[(size_t)s * 32 + lane];
        acc.x += a.x;
        acc.y += a.y;
    }
    acc.x = fmaxf(acc.x + bias.x, 0.f);
    acc.y = fmaxf(acc.y + bias.y, 0.f);
    uint32_t hi, lo;
    split2(acc.x, acc.y, hi, lo);
    ((uint32_t*)AGhi)[(size_t)w * 32 + lane] = hi;
    ((uint32_t*)AGlo)[(size_t)w * 32 + lane] = lo;
}

// ================= fused MLP: AG(bf16) @ W2 -> BN+ReLU -> [@W1next -> Y | pool -> sums] =================
template <int NOUT, bool CHAIN>
__global__ __launch_bounds__(128) void fused_mlp(const __nv_bfloat16* __restrict__ AGhi,
                                                 const __nv_bfloat16* __restrict__ AGlo,
                                                 const __nv_bfloat16* __restrict__ W2hi,
                                                 const __nv_bfloat16* __restrict__ W2lo,
                                                 const float* __restrict__ b2,
                                                 const float* __restrict__ bng,
                                                 const float* __restrict__ bnb,
                                                 const float* __restrict__ bnm,
                                                 const float* __restrict__ bnv,
                                                 const __nv_bfloat16* __restrict__ W1hi,
                                                 const __nv_bfloat16* __restrict__ W1lo,
                                                 const int* __restrict__ batch,
                                                 float* __restrict__ OUT) {
    constexpr int K = 64;
    constexpr int SP = K + 8, SPB = SP * 2;
    constexpr int NT = NOUT / 8;
    extern __shared__ char dsm[];
    uint32_t aHi = smem_u32(dsm);
    uint32_t aLo = aHi + 128 * SPB;
    uint32_t wHi = aLo + 128 * SPB;
    uint32_t wLo = wHi + NOUT * SPB;
    __shared__ float sScale[NOUT];
    __shared__ float sShift[NOUT];

    const int tid = threadIdx.x, warp = tid >> 5, lane = tid & 31;
    const int base = blockIdx.x * 128;

    if (tid < NOUT) {
        float s = bng[tid] * rsqrtf(bnv[tid] + BN_EPS);
        sScale[tid] = s;
        sShift[tid] = (b2[tid] - bnm[tid]) * s + bnb[tid];
    }
    for (int i = tid; i < NOUT * K / 2; i += 128) {
        int byte = i * 4;
        int row = byte >> 7, kb = byte & 127;
        uint32_t off = (uint32_t)row * SPB + kb;
        sts32(wHi + off, ((const uint32_t*)W2hi)[i]);
        sts32(wLo + off, ((const uint32_t*)W2lo)[i]);
    }
    for (int i = tid; i < 128 * 32; i += 128) {
        int row = i >> 5, w = i & 31;
        uint32_t h = 0, l = 0;
        if (base + row < N_NODES) {
            h = ((const uint32_t*)AGhi)[(size_t)(base + row) * 32 + w];
            l = ((const uint32_t*)AGlo)[(size_t)(base + row) * 32 + w];
        }
        uint32_t off = (uint32_t)row * SPB + w * 4;
        sts32(aHi + off, h);
        sts32(aLo + off, l);
    }
    __syncthreads();

    float acc[2][NT][4];
#pragma unroll
    for (int t = 0; t < 2; t++)
#pragma unroll
        for (int n = 0; n < NT; n++)
#pragma unroll
            for (int j = 0; j < 4; j++) acc[t][n][j] = 0.f;

    const int arow = warp * 32 + (lane & 15);
    const int ahalf = lane >> 4;
    const int brow = lane & 7;
    const int bhalf = (lane >> 3) & 1;

#pragma unroll
    for (int s = 0; s < 3; s++) {
        uint32_t Ab = (s == 2) ? aLo : aHi;
        uint32_t Wb = (s == 1) ? wLo : wHi;
#pragma unroll
        for (int k16 = 0; k16 < 4; k16++) {
            uint32_t kbyte = (uint32_t)(k16 * 32);
            uint32_t af0[4], af1[4];
            ldsm4(af0, Ab + (uint32_t)arow * SPB + kbyte + ahalf * 16);
            ldsm4(af1, Ab + (uint32_t)(arow + 16) * SPB + kbyte + ahalf * 16);
#pragma unroll
            for (int n8 = 0; n8 < NT; n8++) {
                uint32_t bf[2];
                ldsm2(bf, Wb + (uint32_t)(n8 * 8 + brow) * SPB + kbyte + bhalf * 16);
                mma_bf16(acc[0][n8], af0, bf);
                mma_bf16(acc[1][n8], af1, bf);
            }
        }
    }

    const int r_in_warp = lane >> 2;
    const int cpair = (lane & 3) * 2;
#pragma unroll
    for (int t = 0; t < 2; t++) {
#pragma unroll
        for (int n8 = 0; n8 < NT; n8++) {
            int c = n8 * 8 + cpair;
            acc[t][n8][0] = fmaxf(acc[t][n8][0] * sScale[c] + sShift[c], 0.f);
            acc[t][n8][1] = fmaxf(acc[t][n8][1] * sScale[c + 1] + sShift[c + 1], 0.f);
            acc[t][n8][2] = fmaxf(acc[t][n8][2] * sScale[c] + sShift[c], 0.f);
            acc[t][n8][3] = fmaxf(acc[t][n8][3] * sScale[c + 1] + sShift[c + 1], 0.f);
        }
    }

    if (!CHAIN) {
        // ===== fused mean-pool: accumulate per-graph partial sums in smem =====
        __shared__ int sbatch[128];
        int node = base + tid;
        sbatch[tid] = (node < N_NODES) ? batch[node] : 0;
        __syncthreads();   // also: all ldmatrix reads done -> W region reusable
        int lastv = N_NODES - 1 - base; if (lastv > 127) lastv = 127;
        int gmin = sbatch[0];
        int gmax = sbatch[lastv];
        int span = gmax - gmin + 1;
        float* pool = (float*)(dsm + 2 * 128 * SPB);   // 27648 B >= 64*96*4
        for (int i = tid; i < span * 96; i += 128) pool[i] = 0.f;
        __syncthreads();
#pragma unroll
        for (int t = 0; t < 2; t++) {
            int rl0 = warp * 32 + t * 16 + r_in_warp;
            int rl1 = rl0 + 8;
            bool v0 = (base + rl0 < N_NODES), v1 = (base + rl1 < N_NODES);
            int g0 = v0 ? (sbatch[rl0] - gmin) : 0;
            int g1 = v1 ? (sbatch[rl1] - gmin) : 0;
#pragma unroll
            for (int n8 = 0; n8 < NT; n8++) {
                int c = n8 * 8 + cpair;
                if (v0) {
                    atomicAdd(&pool[g0 * 96 + c],     acc[t][n8][0]);
                    atomicAdd(&pool[g0 * 96 + c + 1], acc[t][n8][1]);
                }
                if (v1) {
                    atomicAdd(&pool[g1 * 96 + c],     acc[t][n8][2]);
                    atomicAdd(&pool[g1 * 96 + c + 1], acc[t][n8][3]);
                }
            }
        }
        __syncthreads();
        for (int i = tid; i < span * 96; i += 128)
            atomicAdd(&OUT[(gmin + i / 96) * 96 + i % 96], pool[i]);
        return;
    }

    // ---- chained next-layer GEMM1: y_next = a @ W1next (fp32 out) ----
    __syncthreads();
#pragma unroll
    for (int t = 0; t < 2; t++) {
        int rl0 = warp * 32 + t * 16 + r_in_warp;
        int rl1 = rl0 + 8;
#pragma unroll
        for (int n8 = 0; n8 < NT; n8++) {
            int cb = (n8 * 8 + cpair) * 2;
            uint32_t h, l;
            split2(acc[t][n8][0], acc[t][n8][1], h, l);
            sts32(aHi + (uint32_t)rl0 * SPB + cb, h);
            sts32(aLo + (uint32_t)rl0 * SPB + cb, l);
            split2(acc[t][n8][2], acc[t][n8][3], h, l);
            sts32(aHi + (uint32_t)rl1 * SPB + cb, h);
            sts32(aLo + (uint32_t)rl1 * SPB + cb, l);
        }
    }
    for (int i = tid; i < 64 * K / 2; i += 128) {
        int byte = i * 4;
        int row = byte >> 7, kb = byte & 127;
        uint32_t off = (uint32_t)row * SPB + kb;
        sts32(wHi + off, ((const uint32_t*)W1hi)[i]);
        sts32(wLo + off, ((const uint32_t*)W1lo)[i]);
    }
    __syncthreads();

    float acc2[2][8][4];
#pragma unroll
    for (int t = 0; t < 2; t++)
#pragma unroll
        for (int n = 0; n < 8; n++)
#pragma unroll
            for (int j = 0; j < 4; j++) acc2[t][n][j] = 0.f;

#pragma unroll
    for (int s = 0; s < 3; s++) {
        uint32_t Ab = (s == 2) ? aLo : aHi;
        uint32_t Wb = (s == 1) ? wLo : wHi;
#pragma unroll
        for (int k16 = 0; k16 < 4; k16++) {
            uint32_t kbyte = (uint32_t)(k16 * 32);
            uint32_t af0[4], af1[4];
            ldsm4(af0, Ab + (uint32_t)arow * SPB + kbyte + ahalf * 16);
            ldsm4(af1, Ab + (uint32_t)(arow + 16) * SPB + kbyte + ahalf * 16);
#pragma unroll
            for (int n8 = 0; n8 < 8; n8++) {
                uint32_t bf[2];
                ldsm2(bf, Wb + (uint32_t)(n8 * 8 + brow) * SPB + kbyte + bhalf * 16);
                mma_bf16(acc2[0][n8], af0, bf);
                mma_bf16(acc2[1][n8], af1, bf);
            }
        }
    }
#pragma unroll
    for (int t = 0; t < 2; t++) {
        int row0 = base + warp * 32 + t * 16 + r_in_warp;
        int row1 = row0 + 8;
#pragma unroll
        for (int n8 = 0; n8 < 8; n8++) {
            int c = n8 * 8 + cpair;
            if (row0 < N_NODES) *(float2*)(OUT + (size_t)row0 * 64 + c) = make_float2(acc2[t][n8][0], acc2[t][n8][1]);
            if (row1 < N_NODES) *(float2*)(OUT + (size_t)row1 * 64 + c) = make_float2(acc2[t][n8][2], acc2[t][n8][3]);
        }
    }
}

// ================= finalize: out = sums / max(cnts,1) =================
__global__ void finalize_kernel(const float* __restrict__ sums, const int* __restrict__ cnts,
                                float* __restrict__ out) {
    int i = blockIdx.x * blockDim.x + threadIdx.x;
    if (i >= N_GRAPHS * 96) return;
    float c = fmaxf((float)cnts[i / 96], 1.f);
    out[i] = sums[i] / c;
}

// ================= launch =================
extern "C" void kernel_launch(void* const* d_in, const int* in_sizes, int n_in,
                              void* d_out, int out_size) {
    const float* x     = (const float*)d_in[0];
    const void*  ei    = d_in[1];
    const void*  batch = d_in[2];
    const float* P[24];
    for (int i = 0; i < 24; i++) P[i] = (const float*)d_in[3 + i];

    float *y, *sums;
    __nv_bfloat16 *aghi, *aglo, *whi, *wlo;
    int *cnts, *src, *dst, *b32, *flags;
    int *deg, *rowptr, *cursor, *colv, *part, *poff;
    cudaGetSymbolAddress((void**)&y,      g_y);
    cudaGetSymbolAddress((void**)&aghi,   g_aghi);
    cudaGetSymbolAddress((void**)&aglo,   g_aglo);
    cudaGetSymbolAddress((void**)&sums,   g_sums);
    cudaGetSymbolAddress((void**)&cnts,   g_cnts);
    cudaGetSymbolAddress((void**)&src,    g_src);
    cudaGetSymbolAddress((void**)&dst,    g_dst);
    cudaGetSymbolAddress((void**)&b32,    g_batch32);
    cudaGetSymbolAddress((void**)&flags,  g_flags);
    cudaGetSymbolAddress((void**)&deg,    g_deg);
    cudaGetSymbolAddress((void**)&rowptr, g_rowptr);
    cudaGetSymbolAddress((void**)&cursor, g_cursor);
    cudaGetSymbolAddress((void**)&colv,   g_col);
    cudaGetSymbolAddress((void**)&part,   g_part);
    cudaGetSymbolAddress((void**)&poff,   g_poff);
    cudaGetSymbolAddress((void**)&whi,    g_whi);
    cudaGetSymbolAddress((void**)&wlo,    g_wlo);

    const int SM_L0  = (256 + 128) * (136 * 2);   // 104448
    const int SM_F64 = (256 + 128) * (72 * 2);    // 55296
    const int SM_F96 = (256 + 192) * (72 * 2);    // 64512 (pool region reuses W area)
    cudaFuncSetAttribute((const void*)hgemm_l0, cudaFuncAttributeMaxDynamicSharedMemorySize, SM_L0);
    cudaFuncSetAttribute((const void*)fused_mlp<64, true>,  cudaFuncAttributeMaxDynamicSharedMemorySize, SM_F64);
    cudaFuncSetAttribute((const void*)fused_mlp<96, false>, cudaFuncAttributeMaxDynamicSharedMemorySize, SM_F96);

    const int NB = (N_NODES + 127) / 128;          // 782
    const int GB = (N_NODES * 32 + 255) / 256;     // 12500
    const int PREP_B = NB_SCAN + 3 + WB;           // 514

    prep_kernel<<<PREP_B, 256>>>(ei, batch, flags, deg, sums, cnts,
                                 P[0], P[2], P[8], P[10], P[16], P[18], whi, wlo);
    convert_all_kernel<<<EB + NB_SCAN, 256>>>(ei, batch, flags, src, dst, deg, b32, cnts);
    partials_kernel<<<NB_SCAN, SCAN_BS>>>(deg, part);
    scan_partials_kernel<<<1, 512>>>(part, poff);
    rowptr_kernel<<<NB_SCAN, SCAN_BS>>>(deg, poff, rowptr, cursor);
    fill_kernel<<<EB, 256>>>(src, dst, cursor, colv);

    const int O_W10 = 0, O_W20 = 8192, O_W11 = 12288, O_W21 = 16384, O_W12 = 20480, O_W22 = 24576;

    hgemm_l0<<<NB, 128, SM_L0>>>(x, whi + O_W10, wlo + O_W10, y);
    gather_kernel<<<GB, 256>>>(y, rowptr, colv, P[1], aghi, aglo);
    fused_mlp<64, true><<<NB, 128, SM_F64>>>(aghi, aglo, whi + O_W20, wlo + O_W20,
                                             P[3], P[4], P[5], P[6], P[7],
                                             whi + O_W11, wlo + O_W11, nullptr, y);
    gather_kernel<<<GB, 256>>>(y, rowptr, colv, P[9], aghi, aglo);
    fused_mlp<64, true><<<NB, 128, SM_F64>>>(aghi, aglo, whi + O_W21, wlo + O_W21,
                                             P[11], P[12], P[13], P[14], P[15],
                                             whi + O_W12, wlo + O_W12, nullptr, y);
    gather_kernel<<<GB, 256>>>(y, rowptr, colv, P[17], aghi, aglo);
    fused_mlp<96, false><<<NB, 128, SM_F96>>>(aghi, aglo, whi + O_W22, wlo + O_W22,
                                              P[19], P[20], P[21], P[22], P[23],
                                              nullptr, nullptr, b32, sums);

    finalize_kernel<<<(N_GRAPHS * 96 + 255) / 256, 256>>>(sums, cnts, (float*)d_out);
}

// round 10
// speedup vs baseline: 1.3695x; 1.3695x over previous
#include <cuda_runtime.h>
#include <cuda_bf16.h>
#include <cstdint>

#define N_NODES 100000
#define N_EDGES 600000
#define N_GRAPHS 64
#define BN_EPS 1e-5f
#define SCAN_BS 256
#define NB_SCAN ((N_NODES + SCAN_BS - 1) / SCAN_BS)   // 391
#define EB ((N_EDGES + 255) / 256)                     // 2344
#define WTOT 30720
#define WB ((WTOT + 255) / 256)                        // 120

// ================= helpers =================
__device__ __forceinline__ uint32_t smem_u32(const void* p) {
    uint32_t a;
    asm("{ .reg .u64 t; cvta.to.shared.u64 t, %1; cvt.u32.u64 %0, t; }" : "=r"(a) : "l"(p));
    return a;
}
__device__ __forceinline__ void sts32(uint32_t addr, uint32_t v) {
    asm volatile("st.shared.b32 [%0], %1;" :: "r"(addr), "r"(v));
}
__device__ __forceinline__ void ldsm4(uint32_t r[4], uint32_t a) {
    asm volatile("ldmatrix.sync.aligned.m8n8.x4.shared.b16 {%0,%1,%2,%3}, [%4];"
                 : "=r"(r[0]), "=r"(r[1]), "=r"(r[2]), "=r"(r[3]) : "r"(a));
}
__device__ __forceinline__ void ldsm2(uint32_t r[2], uint32_t a) {
    asm volatile("ldmatrix.sync.aligned.m8n8.x2.shared.b16 {%0,%1}, [%2];"
                 : "=r"(r[0]), "=r"(r[1]) : "r"(a));
}
__device__ __forceinline__ void mma_bf16(float c[4], const uint32_t a[4], const uint32_t b[2]) {
    asm volatile("mma.sync.aligned.m16n8k16.row.col.f32.bf16.bf16.f32 "
                 "{%0,%1,%2,%3}, {%4,%5,%6,%7}, {%8,%9}, {%0,%1,%2,%3};"
                 : "+f"(c[0]), "+f"(c[1]), "+f"(c[2]), "+f"(c[3])
                 : "r"(a[0]), "r"(a[1]), "r"(a[2]), "r"(a[3]), "r"(b[0]), "r"(b[1]));
}
__device__ __forceinline__ void split2(float a, float b, uint32_t& hi, uint32_t& lo) {
    __nv_bfloat16 ha = __float2bfloat16(a), hb = __float2bfloat16(b);
    __nv_bfloat16 la = __float2bfloat16(a - __bfloat162float(ha));
    __nv_bfloat16 lb = __float2bfloat16(b - __bfloat162float(hb));
    __nv_bfloat162 H; H.x = ha; H.y = hb;
    __nv_bfloat162 L; L.x = la; L.y = lb;
    hi = *(uint32_t*)&H; lo = *(uint32_t*)&L;
}

// ================= scratch =================
__device__ float g_y[(size_t)N_NODES * 64];
__device__ __nv_bfloat16 g_aghi[(size_t)N_NODES * 64];
__device__ __nv_bfloat16 g_aglo[(size_t)N_NODES * 64];
__device__ float g_sums[N_GRAPHS * 96];
__device__ int   g_cnts[N_GRAPHS];
__device__ int   g_src[N_EDGES];
__device__ int   g_dst[N_EDGES];
__device__ int   g_batch32[N_NODES];
__device__ int   g_deg[N_NODES];
__device__ int   g_rowptr[N_NODES + 1];
__device__ int   g_cursor[N_NODES];
__device__ int   g_col[N_EDGES];
__device__ int   g_part[NB_SCAN];
__device__ int   g_poff[NB_SCAN];
__device__ int   g_flags[2];
__device__ __nv_bfloat16 g_whi[WTOT];
__device__ __nv_bfloat16 g_wlo[WTOT];

// ================= mega-prep: detect dtypes + zero deg/sums/cnts + weight split =================
__global__ void prep_kernel(const void* ei, const void* batch, int* flags,
                            int* __restrict__ deg, float* __restrict__ sums,
                            int* __restrict__ cnts,
                            const float* w10, const float* w20, const float* w11,
                            const float* w21, const float* w12, const float* w22,
                            __nv_bfloat16* __restrict__ whi, __nv_bfloat16* __restrict__ wlo) {
    int b = blockIdx.x, t = threadIdx.x;
    if (b < NB_SCAN) {
        int i = b * 256 + t;
        if (i < N_NODES) deg[i] = 0;
    } else if (b == NB_SCAN || b == NB_SCAN + 1) {
        __shared__ int ok;
        if (t == 0) ok = 1;
        __syncthreads();
        int which = b - NB_SCAN;
        const void* p = (which == 0) ? ei : batch;
        long long n64_max = (which == 0) ? (long long)N_EDGES : (long long)N_NODES / 2;
        int maxval = (which == 0) ? N_NODES : N_GRAPHS;
        long long idx = (long long)t * (n64_max - 1) / 255;
        long long v = ((const long long*)p)[idx];
        if (v < 0 || v >= maxval) atomicAnd(&ok, 0);
        __syncthreads();
        if (t == 0) flags[which] = ok;
    } else if (b == NB_SCAN + 2) {
        for (int i = t; i < N_GRAPHS * 96; i += 256) sums[i] = 0.f;
        if (t < N_GRAPHS) cnts[t] = 0;
    } else {
        int i = (b - (NB_SCAN + 3)) * 256 + t;
        if (i >= WTOT) return;
        const float* src; int K, off;
        if      (i < 8192)  { src = w10; K = 128; off = 0; }
        else if (i < 12288) { src = w20; K = 64;  off = 8192; }
        else if (i < 16384) { src = w11; K = 64;  off = 12288; }
        else if (i < 20480) { src = w21; K = 64;  off = 16384; }
        else if (i < 24576) { src = w12; K = 64;  off = 20480; }
        else                { src = w22; K = 64;  off = 24576; }
        int N = (i < 24576) ? 64 : 96;
        int local = i - off;
        int n = local / K, k = local % K;
        float v = src[k * N + n];
        __nv_bfloat16 h = __float2bfloat16(v);
        whi[i] = h;
        wlo[i] = __float2bfloat16(v - __bfloat162float(h));
    }
}

// ================= convert edges + batch (one grid); also counts nodes/graph =================
__global__ void convert_all_kernel(const void* ei, const void* batch, const int* flags,
                                   int* __restrict__ src, int* __restrict__ dst,
                                   int* __restrict__ deg, int* __restrict__ b32,
                                   int* __restrict__ cnts) {
    int b = blockIdx.x, t = threadIdx.x;
    if (b < EB) {
        int i = b * 256 + t;
        if (i >= N_EDGES) return;
        int s, d;
        if (flags[0]) {
            const long long* p = (const long long*)ei;
            s = (int)p[i]; d = (int)p[N_EDGES + i];
        } else {
            const int* p = (const int*)ei;
            s = p[i]; d = p[N_EDGES + i];
        }
        src[i] = s; dst[i] = d;
        atomicAdd(&deg[d], 1);
    } else {
        int i = (b - EB) * 256 + t;
        if (i >= N_NODES) return;
        int v;
        if (flags[1]) v = (int)((const long long*)batch)[i];
        else          v = ((const int*)batch)[i];
        b32[i] = v;
        atomicAdd(&cnts[v], 1);
    }
}

// ================= scan chain =================
__global__ void partials_kernel(const int* __restrict__ deg, int* __restrict__ part) {
    __shared__ int sm[SCAN_BS];
    int i = blockIdx.x * SCAN_BS + threadIdx.x;
    sm[threadIdx.x] = (i < N_NODES) ? deg[i] : 0;
    __syncthreads();
#pragma unroll
    for (int s = SCAN_BS / 2; s > 0; s >>= 1) {
        if (threadIdx.x < s) sm[threadIdx.x] += sm[threadIdx.x + s];
        __syncthreads();
    }
    if (threadIdx.x == 0) part[blockIdx.x] = sm[0];
}
__global__ void scan_partials_kernel(const int* __restrict__ part, int* __restrict__ poff) {
    __shared__ int sm[512];
    int t = threadIdx.x;
    int v = (t < NB_SCAN) ? part[t] : 0;
    sm[t] = v;
    __syncthreads();
#pragma unroll
    for (int off = 1; off < 512; off <<= 1) {
        int x = (t >= off) ? sm[t - off] : 0;
        __syncthreads();
        sm[t] += x;
        __syncthreads();
    }
    if (t < NB_SCAN) poff[t] = sm[t] - v;
}
__global__ void rowptr_kernel(const int* __restrict__ deg, const int* __restrict__ poff,
                              int* __restrict__ rowptr, int* __restrict__ cursor) {
    __shared__ int sm[SCAN_BS];
    int b = blockIdx.x, t = threadIdx.x;
    int i = b * SCAN_BS + t;
    int v = (i < N_NODES) ? deg[i] : 0;
    sm[t] = v;
    __syncthreads();
    for (int off = 1; off < SCAN_BS; off <<= 1) {
        int x = (t >= off) ? sm[t - off] : 0;
        __syncthreads();
        sm[t] += x;
        __syncthreads();
    }
    if (i < N_NODES) {
        int r = poff[b] + sm[t] - v;
        rowptr[i] = r;
        cursor[i] = r;
    }
    if (i == N_NODES - 1) rowptr[N_NODES] = poff[b] + sm[t];
}
__global__ void fill_kernel(const int* __restrict__ src, const int* __restrict__ dst,
                            int* __restrict__ cursor, int* __restrict__ col) {
    int e = blockIdx.x * blockDim.x + threadIdx.x;
    if (e >= N_EDGES) return;
    int d = dst[e];
    int pos = atomicAdd(&cursor[d], 1);
    col[pos] = src[e];
}

// ================= standalone GEMM layer0: Y = X @ W1 (K=128, N=64), fp32 out =================
__global__ __launch_bounds__(128) void hgemm_l0(const float* __restrict__ X,
                                                const __nv_bfloat16* __restrict__ Whi,
                                                const __nv_bfloat16* __restrict__ Wlo,
                                                float* __restrict__ Y) {
    constexpr int K = 128, N = 64;
    constexpr int SP = K + 8, SPB = SP * 2, NT = N / 8;
    extern __shared__ char dsm[];
    uint32_t aHi = smem_u32(dsm);
    uint32_t aLo = aHi + 128 * SPB;
    uint32_t wHi = aLo + 128 * SPB;
    uint32_t wLo = wHi + N * SPB;

    const int tid = threadIdx.x, warp = tid >> 5, lane = tid & 31;
    const int base = blockIdx.x * 128;

    for (int i = tid; i < N * K / 2; i += 128) {
        int byte = i * 4;
        int row = byte / (K * 2), kb = byte - row * (K * 2);
        uint32_t off = (uint32_t)row * SPB + kb;
        sts32(wHi + off, ((const uint32_t*)Whi)[i]);
        sts32(wLo + off, ((const uint32_t*)Wlo)[i]);
    }
    constexpr int N4 = K / 4;
    for (int i = tid; i < 128 * N4; i += 128) {
        int row = i / N4, c4 = i - row * N4, col = c4 * 4;
        float4 v = make_float4(0.f, 0.f, 0.f, 0.f);
        if (base + row < N_NODES) v = ((const float4*)X)[(size_t)(base + row) * N4 + c4];
        uint32_t h01, l01, h23, l23;
        split2(v.x, v.y, h01, l01);
        split2(v.z, v.w, h23, l23);
        uint32_t off = (uint32_t)row * SPB + col * 2;
        sts32(aHi + off, h01); sts32(aHi + off + 4, h23);
        sts32(aLo + off, l01); sts32(aLo + off + 4, l23);
    }
    __syncthreads();

    float acc[2][NT][4];
#pragma unroll
    for (int t = 0; t < 2; t++)
#pragma unroll
        for (int n = 0; n < NT; n++)
#pragma unroll
            for (int j = 0; j < 4; j++) acc[t][n][j] = 0.f;

    const int arow = warp * 32 + (lane & 15);
    const int ahalf = lane >> 4;
    const int brow = lane & 7;
    const int bhalf = (lane >> 3) & 1;

#pragma unroll
    for (int s = 0; s < 3; s++) {
        uint32_t Ab = (s == 2) ? aLo : aHi;
        uint32_t Wb = (s == 1) ? wLo : wHi;
#pragma unroll
        for (int k16 = 0; k16 < K / 16; k16++) {
            uint32_t kbyte = (uint32_t)(k16 * 16) * 2;
            uint32_t af0[4], af1[4];
            ldsm4(af0, Ab + (uint32_t)arow * SPB + kbyte + ahalf * 16);
            ldsm4(af1, Ab + (uint32_t)(arow + 16) * SPB + kbyte + ahalf * 16);
#pragma unroll
            for (int n8 = 0; n8 < NT; n8++) {
                uint32_t bf[2];
                ldsm2(bf, Wb + (uint32_t)(n8 * 8 + brow) * SPB + kbyte + bhalf * 16);
                mma_bf16(acc[0][n8], af0, bf);
                mma_bf16(acc[1][n8], af1, bf);
            }
        }
    }
    const int r_in_warp = lane >> 2;
    const int cpair = (lane & 3) * 2;
#pragma unroll
    for (int t = 0; t < 2; t++) {
        int row0 = base + warp * 32 + t * 16 + r_in_warp;
        int row1 = row0 + 8;
#pragma unroll
        for (int n8 = 0; n8 < NT; n8++) {
            int col = n8 * 8 + cpair;
            if (row0 < N_NODES) *(float2*)(Y + (size_t)row0 * N + col) = make_float2(acc[t][n8][0], acc[t][n8][1]);
            if (row1 < N_NODES) *(float2*)(Y + (size_t)row1 * N + col) = make_float2(acc[t][n8][2], acc[t][n8][3]);
        }
    }
}

// ================= gather: AG = split(ReLU(gathersum + b1)) as bf16 hi/lo =================
__global__ __launch_bounds__(256) void gather_kernel(const float* __restrict__ Y,
                                                     const int* __restrict__ rowptr,
                                                     const int* __restrict__ col,
                                                     const float* __restrict__ b1,
                                                     __nv_bfloat16* __restrict__ AGhi,
                                                     __nv_bfloat16* __restrict__ AGlo) {
    int w = (blockIdx.x * blockDim.x + threadIdx.x) >> 5;
    int lane = threadIdx.x & 31;
    if (w >= N_NODES) return;
    const float2* y2 = (const float2*)Y;
    float2 bias = ((const float2*)b1)[lane];
    int r0 = rowptr[w], r1 = rowptr[w + 1];
    float2 acc = y2[(size_t)w * 32 + lane];
    int e = r0;
    for (; e + 3 < r1; e += 4) {
        int s0 = col[e], s1 = col[e + 1], s2 = col[e + 2], s3 = col[e + 3];
        float2 a = y2[(size_t)s0 * 32 + lane];
        float2 b = y2[(size_t)s1 * 32 + lane];
        float2 c = y2[(size_t)s2 * 32 + lane];
        float2 d = y2[(size_t)s3 * 32 + lane];
        acc.x += (a.x + b.x) + (c.x + d.x);
        acc.y += (a.y + b.y) + (c.y + d.y);
    }
    if (e + 1 < r1) {
        int s0 = col[e], s1 = col[e + 1];
        float2 a = y2[(size_t)s0 * 32 + lane];
        float2 b = y2[(size_t)s1 * 32 + lane];
        acc.x += a.x + b.x;
        acc.y += a.y + b.y;
        e += 2;
    }
    if (e < r1) {
        int s = col[e];
        float2 a = y2[(size_t)s * 32 + lane];
        acc.x += a.x;
        acc.y += a.y;
    }
    acc.x = fmaxf(acc.x + bias.x, 0.f);
    acc.y = fmaxf(acc.y + bias.y, 0.f);
    uint32_t hi, lo;
    split2(acc.x, acc.y, hi, lo);
    ((uint32_t*)AGhi)[(size_t)w * 32 + lane] = hi;
    ((uint32_t*)AGlo)[(size_t)w * 32 + lane] = lo;
}

// ================= fused MLP: AG(bf16) @ W2 -> BN+ReLU -> [@W1next -> Y | pool -> sums] =================
template <int NOUT, bool CHAIN>
__global__ __launch_bounds__(128) void fused_mlp(const __nv_bfloat16* __restrict__ AGhi,
                                                 const __nv_bfloat16* __restrict__ AGlo,
                                                 const __nv_bfloat16* __restrict__ W2hi,
                                                 const __nv_bfloat16* __restrict__ W2lo,
                                                 const float* __restrict__ b2,
                                                 const float* __restrict__ bng,
                                                 const float* __restrict__ bnb,
                                                 const float* __restrict__ bnm,
                                                 const float* __restrict__ bnv,
                                                 const __nv_bfloat16* __restrict__ W1hi,
                                                 const __nv_bfloat16* __restrict__ W1lo,
                                                 const int* __restrict__ batch,
                                                 float* __restrict__ OUT) {
    constexpr int K = 64;
    constexpr int SP = K + 8, SPB = SP * 2;
    constexpr int NT = NOUT / 8;
    extern __shared__ char dsm[];
    uint32_t aHi = smem_u32(dsm);
    uint32_t aLo = aHi + 128 * SPB;
    uint32_t wHi = aLo + 128 * SPB;
    uint32_t wLo = wHi + NOUT * SPB;
    __shared__ float sScale[NOUT];
    __shared__ float sShift[NOUT];

    const int tid = threadIdx.x, warp = tid >> 5, lane = tid & 31;
    const int base = blockIdx.x * 128;

    if (tid < NOUT) {
        float s = bng[tid] * rsqrtf(bnv[tid] + BN_EPS);
        sScale[tid] = s;
        sShift[tid] = (b2[tid] - bnm[tid]) * s + bnb[tid];
    }
    for (int i = tid; i < NOUT * K / 2; i += 128) {
        int byte = i * 4;
        int row = byte >> 7, kb = byte & 127;
        uint32_t off = (uint32_t)row * SPB + kb;
        sts32(wHi + off, ((const uint32_t*)W2hi)[i]);
        sts32(wLo + off, ((const uint32_t*)W2lo)[i]);
    }
    for (int i = tid; i < 128 * 32; i += 128) {
        int row = i >> 5, w = i & 31;
        uint32_t h = 0, l = 0;
        if (base + row < N_NODES) {
            h = ((const uint32_t*)AGhi)[(size_t)(base + row) * 32 + w];
            l = ((const uint32_t*)AGlo)[(size_t)(base + row) * 32 + w];
        }
        uint32_t off = (uint32_t)row * SPB + w * 4;
        sts32(aHi + off, h);
        sts32(aLo + off, l);
    }
    __syncthreads();

    float acc[2][NT][4];
#pragma unroll
    for (int t = 0; t < 2; t++)
#pragma unroll
        for (int n = 0; n < NT; n++)
#pragma unroll
            for (int j = 0; j < 4; j++) acc[t][n][j] = 0.f;

    const int arow = warp * 32 + (lane & 15);
    const int ahalf = lane >> 4;
    const int brow = lane & 7;
    const int bhalf = (lane >> 3) & 1;

#pragma unroll
    for (int s = 0; s < 3; s++) {
        uint32_t Ab = (s == 2) ? aLo : aHi;
        uint32_t Wb = (s == 1) ? wLo : wHi;
#pragma unroll
        for (int k16 = 0; k16 < 4; k16++) {
            uint32_t kbyte = (uint32_t)(k16 * 32);
            uint32_t af0[4], af1[4];
            ldsm4(af0, Ab + (uint32_t)arow * SPB + kbyte + ahalf * 16);
            ldsm4(af1, Ab + (uint32_t)(arow + 16) * SPB + kbyte + ahalf * 16);
#pragma unroll
            for (int n8 = 0; n8 < NT; n8++) {
                uint32_t bf[2];
                ldsm2(bf, Wb + (uint32_t)(n8 * 8 + brow) * SPB + kbyte + bhalf * 16);
                mma_bf16(acc[0][n8], af0, bf);
                mma_bf16(acc[1][n8], af1, bf);
            }
        }
    }

    const int r_in_warp = lane >> 2;
    const int cpair = (lane & 3) * 2;
#pragma unroll
    for (int t = 0; t < 2; t++) {
#pragma unroll
        for (int n8 = 0; n8 < NT; n8++) {
            int c = n8 * 8 + cpair;
            acc[t][n8][0] = fmaxf(acc[t][n8][0] * sScale[c] + sShift[c], 0.f);
            acc[t][n8][1] = fmaxf(acc[t][n8][1] * sScale[c + 1] + sShift[c + 1], 0.f);
            acc[t][n8][2] = fmaxf(acc[t][n8][2] * sScale[c] + sShift[c], 0.f);
            acc[t][n8][3] = fmaxf(acc[t][n8][3] * sScale[c + 1] + sShift[c + 1], 0.f);
        }
    }

    if (!CHAIN) {
        // ===== fused mean-pool, atomic-free in smem =====
        // Store the 128x96 output tile to smem, then threads 0..95 run-length
        // reduce over the sorted batch ids (one global atomicAdd per run).
        __shared__ int sbatch[128];
        int node = base + tid;
        sbatch[tid] = (node < N_NODES) ? batch[node] : -1;
        __syncthreads();   // ldmatrix reads done -> staging region reusable
        float* ftile = (float*)dsm;   // 128*96*4 = 49152 B <= 64512
#pragma unroll
        for (int t = 0; t < 2; t++) {
            int rl0 = warp * 32 + t * 16 + r_in_warp;
            int rl1 = rl0 + 8;
#pragma unroll
            for (int n8 = 0; n8 < NT; n8++) {
                int c = n8 * 8 + cpair;
                ftile[rl0 * 96 + c]     = acc[t][n8][0];
                ftile[rl0 * 96 + c + 1] = acc[t][n8][1];
                ftile[rl1 * 96 + c]     = acc[t][n8][2];
                ftile[rl1 * 96 + c + 1] = acc[t][n8][3];
            }
        }
        __syncthreads();
        if (tid < 96) {
            int cur = sbatch[0];
            float a = 0.f;
            for (int n = 0; n < 128; n++) {
                int g = sbatch[n];
                if (g < 0) break;
                float v = ftile[n * 96 + tid];
                if (g != cur) { atomicAdd(&OUT[cur * 96 + tid], a); a = 0.f; cur = g; }
                a += v;
            }
            atomicAdd(&OUT[cur * 96 + tid], a);
        }
        return;
    }

    // ---- chained next-layer GEMM1: y_next = a @ W1next (fp32 out) ----
    __syncthreads();
#pragma unroll
    for (int t = 0; t < 2; t++) {
        int rl0 = warp * 32 + t * 16 + r_in_warp;
        int rl1 = rl0 + 8;
#pragma unroll
        for (int n8 = 0; n8 < NT; n8++) {
            int cb = (n8 * 8 + cpair) * 2;
            uint32_t h, l;
            split2(acc[t][n8][0], acc[t][n8][1], h, l);
            sts32(aHi + (uint32_t)rl0 * SPB + cb, h);
            sts32(aLo + (uint32_t)rl0 * SPB + cb, l);
            split2(acc[t][n8][2], acc[t][n8][3], h, l);
            sts32(aHi + (uint32_t)rl1 * SPB + cb, h);
            sts32(aLo + (uint32_t)rl1 * SPB + cb, l);
        }
    }
    for (int i = tid; i < 64 * K / 2; i += 128) {
        int byte = i * 4;
        int row = byte >> 7, kb = byte & 127;
        uint32_t off = (uint32_t)row * SPB + kb;
        sts32(wHi + off, ((const uint32_t*)W1hi)[i]);
        sts32(wLo + off, ((const uint32_t*)W1lo)[i]);
    }
    __syncthreads();

    float acc2[2][8][4];
#pragma unroll
    for (int t = 0; t < 2; t++)
#pragma unroll
        for (int n = 0; n < 8; n++)
#pragma unroll
            for (int j = 0; j < 4; j++) acc2[t][n][j] = 0.f;

#pragma unroll
    for (int s = 0; s < 3; s++) {
        uint32_t Ab = (s == 2) ? aLo : aHi;
        uint32_t Wb = (s == 1) ? wLo : wHi;
#pragma unroll
        for (int k16 = 0; k16 < 4; k16++) {
            uint32_t kbyte = (uint32_t)(k16 * 32);
            uint32_t af0[4], af1[4];
            ldsm4(af0, Ab + (uint32_t)arow * SPB + kbyte + ahalf * 16);
            ldsm4(af1, Ab + (uint32_t)(arow + 16) * SPB + kbyte + ahalf * 16);
#pragma unroll
            for (int n8 = 0; n8 < 8; n8++) {
                uint32_t bf[2];
                ldsm2(bf, Wb + (uint32_t)(n8 * 8 + brow) * SPB + kbyte + bhalf * 16);
                mma_bf16(acc2[0][n8], af0, bf);
                mma_bf16(acc2[1][n8], af1, bf);
            }
        }
    }
#pragma unroll
    for (int t = 0; t < 2; t++) {
        int row0 = base + warp * 32 + t * 16 + r_in_warp;
        int row1 = row0 + 8;
#pragma unroll
        for (int n8 = 0; n8 < 8; n8++) {
            int c = n8 * 8 + cpair;
            if (row0 < N_NODES) *(float2*)(OUT + (size_t)row0 * 64 + c) = make_float2(acc2[t][n8][0], acc2[t][n8][1]);
            if (row1 < N_NODES) *(float2*)(OUT + (size_t)row1 * 64 + c) = make_float2(acc2[t][n8][2], acc2[t][n8][3]);
        }
    }
}

// ================= finalize: out = sums / max(cnts,1) =================
__global__ void finalize_kernel(const float* __restrict__ sums, const int* __restrict__ cnts,
                                float* __restrict__ out) {
    int i = blockIdx.x * blockDim.x + threadIdx.x;
    if (i >= N_GRAPHS * 96) return;
    float c = fmaxf((float)cnts[i / 96], 1.f);
    out[i] = sums[i] / c;
}

// ================= launch =================
extern "C" void kernel_launch(void* const* d_in, const int* in_sizes, int n_in,
                              void* d_out, int out_size) {
    const float* x     = (const float*)d_in[0];
    const void*  ei    = d_in[1];
    const void*  batch = d_in[2];
    const float* P[24];
    for (int i = 0; i < 24; i++) P[i] = (const float*)d_in[3 + i];

    float *y, *sums;
    __nv_bfloat16 *aghi, *aglo, *whi, *wlo;
    int *cnts, *src, *dst, *b32, *flags;
    int *deg, *rowptr, *cursor, *colv, *part, *poff;
    cudaGetSymbolAddress((void**)&y,      g_y);
    cudaGetSymbolAddress((void**)&aghi,   g_aghi);
    cudaGetSymbolAddress((void**)&aglo,   g_aglo);
    cudaGetSymbolAddress((void**)&sums,   g_sums);
    cudaGetSymbolAddress((void**)&cnts,   g_cnts);
    cudaGetSymbolAddress((void**)&src,    g_src);
    cudaGetSymbolAddress((void**)&dst,    g_dst);
    cudaGetSymbolAddress((void**)&b32,    g_batch32);
    cudaGetSymbolAddress((void**)&flags,  g_flags);
    cudaGetSymbolAddress((void**)&deg,    g_deg);
    cudaGetSymbolAddress((void**)&rowptr, g_rowptr);
    cudaGetSymbolAddress((void**)&cursor, g_cursor);
    cudaGetSymbolAddress((void**)&colv,   g_col);
    cudaGetSymbolAddress((void**)&part,   g_part);
    cudaGetSymbolAddress((void**)&poff,   g_poff);
    cudaGetSymbolAddress((void**)&whi,    g_whi);
    cudaGetSymbolAddress((void**)&wlo,    g_wlo);

    const int SM_L0  = (256 + 128) * (136 * 2);   // 104448
    const int SM_F64 = (256 + 128) * (72 * 2);    // 55296
    const int SM_F96 = (256 + 192) * (72 * 2);    // 64512 (>= 49152 ftile)
    cudaFuncSetAttribute((const void*)hgemm_l0, cudaFuncAttributeMaxDynamicSharedMemorySize, SM_L0);
    cudaFuncSetAttribute((const void*)fused_mlp<64, true>,  cudaFuncAttributeMaxDynamicSharedMemorySize, SM_F64);
    cudaFuncSetAttribute((const void*)fused_mlp<96, false>, cudaFuncAttributeMaxDynamicSharedMemorySize, SM_F96);

    const int NB = (N_NODES + 127) / 128;          // 782
    const int GB = (N_NODES * 32 + 255) / 256;     // 12500
    const int PREP_B = NB_SCAN + 3 + WB;           // 514

    prep_kernel<<<PREP_B, 256>>>(ei, batch, flags, deg, sums, cnts,
                                 P[0], P[2], P[8], P[10], P[16], P[18], whi, wlo);
    convert_all_kernel<<<EB + NB_SCAN, 256>>>(ei, batch, flags, src, dst, deg, b32, cnts);
    partials_kernel<<<NB_SCAN, SCAN_BS>>>(deg, part);
    scan_partials_kernel<<<1, 512>>>(part, poff);
    rowptr_kernel<<<NB_SCAN, SCAN_BS>>>(deg, poff, rowptr, cursor);
    fill_kernel<<<EB, 256>>>(src, dst, cursor, colv);

    const int O_W10 = 0, O_W20 = 8192, O_W11 = 12288, O_W21 = 16384, O_W12 = 20480, O_W22 = 24576;

    hgemm_l0<<<NB, 128, SM_L0>>>(x, whi + O_W10, wlo + O_W10, y);
    gather_kernel<<<GB, 256>>>(y, rowptr, colv, P[1], aghi, aglo);
    fused_mlp<64, true><<<NB, 128, SM_F64>>>(aghi, aglo, whi + O_W20, wlo + O_W20,
                                             P[3], P[4], P[5], P[6], P[7],
                                             whi + O_W11, wlo + O_W11, nullptr, y);
    gather_kernel<<<GB, 256>>>(y, rowptr, colv, P[9], aghi, aglo);
    fused_mlp<64, true><<<NB, 128, SM_F64>>>(aghi, aglo, whi + O_W21, wlo + O_W21,
                                             P[11], P[12], P[13], P[14], P[15],
                                             whi + O_W12, wlo + O_W12, nullptr, y);
    gather_kernel<<<GB, 256>>>(y, rowptr, colv, P[17], aghi, aglo);
    fused_mlp<96, false><<<NB, 128, SM_F96>>>(aghi, aglo, whi + O_W22, wlo + O_W22,
                                              P[19], P[20], P[21], P[22], P[23],
                                              nullptr, nullptr, b32, sums);

    finalize_kernel<<<(N_GRAPHS * 96 + 255) / 256, 256>>>(sums, cnts, (float*)d_out);
}

// round 11
// speedup vs baseline: 1.5860x; 1.1581x over previous
#include <cuda_runtime.h>
#include <cuda_bf16.h>
#include <cstdint>

#define N_NODES 100000
#define N_EDGES 600000
#define N_GRAPHS 64
#define BN_EPS 1e-5f
#define SCAN_BS 256
#define NB_SCAN ((N_NODES + SCAN_BS - 1) / SCAN_BS)   // 391
#define EB ((N_EDGES + 255) / 256)                     // 2344
#define WTOT 30720
#define WB ((WTOT + 255) / 256)                        // 120

// ================= helpers =================
__device__ __forceinline__ uint32_t smem_u32(const void* p) {
    uint32_t a;
    asm("{ .reg .u64 t; cvta.to.shared.u64 t, %1; cvt.u32.u64 %0, t; }" : "=r"(a) : "l"(p));
    return a;
}
__device__ __forceinline__ void sts32(uint32_t addr, uint32_t v) {
    asm volatile("st.shared.b32 [%0], %1;" :: "r"(addr), "r"(v));
}
__device__ __forceinline__ void ldsm4(uint32_t r[4], uint32_t a) {
    asm volatile("ldmatrix.sync.aligned.m8n8.x4.shared.b16 {%0,%1,%2,%3}, [%4];"
                 : "=r"(r[0]), "=r"(r[1]), "=r"(r[2]), "=r"(r[3]) : "r"(a));
}
__device__ __forceinline__ void ldsm2(uint32_t r[2], uint32_t a) {
    asm volatile("ldmatrix.sync.aligned.m8n8.x2.shared.b16 {%0,%1}, [%2];"
                 : "=r"(r[0]), "=r"(r[1]) : "r"(a));
}
__device__ __forceinline__ void mma_bf16(float c[4], const uint32_t a[4], const uint32_t b[2]) {
    asm volatile("mma.sync.aligned.m16n8k16.row.col.f32.bf16.bf16.f32 "
                 "{%0,%1,%2,%3}, {%4,%5,%6,%7}, {%8,%9}, {%0,%1,%2,%3};"
                 : "+f"(c[0]), "+f"(c[1]), "+f"(c[2]), "+f"(c[3])
                 : "r"(a[0]), "r"(a[1]), "r"(a[2]), "r"(a[3]), "r"(b[0]), "r"(b[1]));
}
__device__ __forceinline__ void split2(float a, float b, uint32_t& hi, uint32_t& lo) {
    __nv_bfloat16 ha = __float2bfloat16(a), hb = __float2bfloat16(b);
    __nv_bfloat16 la = __float2bfloat16(a - __bfloat162float(ha));
    __nv_bfloat16 lb = __float2bfloat16(b - __bfloat162float(hb));
    __nv_bfloat162 H; H.x = ha; H.y = hb;
    __nv_bfloat162 L; L.x = la; L.y = lb;
    hi = *(uint32_t*)&H; lo = *(uint32_t*)&L;
}

// ================= scratch =================
__device__ float g_y[(size_t)N_NODES * 64];
__device__ __nv_bfloat16 g_aghi[(size_t)N_NODES * 64];
__device__ __nv_bfloat16 g_aglo[(size_t)N_NODES * 64];
__device__ float g_f[(size_t)N_NODES * 96];
__device__ float g_sums[N_GRAPHS * 96];
__device__ int   g_cnts[N_GRAPHS];
__device__ int   g_batch32[N_NODES];
__device__ int   g_deg[N_NODES];
__device__ int   g_rowptr[N_NODES + 1];
__device__ int   g_cursor[N_NODES];
__device__ int   g_col[N_EDGES];
__device__ unsigned long long g_scanstate[NB_SCAN];
__device__ int   g_flags[2];
__device__ __nv_bfloat16 g_whi[WTOT];
__device__ __nv_bfloat16 g_wlo[WTOT];

// ================= mega-prep: detect dtypes + zero deg/sums/cnts/scanstate + weight split =================
__global__ void prep_kernel(const void* ei, const void* batch, int* flags,
                            int* __restrict__ deg, float* __restrict__ sums,
                            int* __restrict__ cnts, unsigned long long* __restrict__ sstate,
                            const float* w10, const float* w20, const float* w11,
                            const float* w21, const float* w12, const float* w22,
                            __nv_bfloat16* __restrict__ whi, __nv_bfloat16* __restrict__ wlo) {
    int b = blockIdx.x, t = threadIdx.x;
    if (b < NB_SCAN) {
        int i = b * 256 + t;
        if (i < N_NODES) deg[i] = 0;
        if (t == 0) sstate[b] = 0ULL;
    } else if (b == NB_SCAN || b == NB_SCAN + 1) {
        __shared__ int ok;
        if (t == 0) ok = 1;
        __syncthreads();
        int which = b - NB_SCAN;
        const void* p = (which == 0) ? ei : batch;
        long long n64_max = (which == 0) ? (long long)N_EDGES : (long long)N_NODES / 2;
        int maxval = (which == 0) ? N_NODES : N_GRAPHS;
        long long idx = (long long)t * (n64_max - 1) / 255;
        long long v = ((const long long*)p)[idx];
        if (v < 0 || v >= maxval) atomicAnd(&ok, 0);
        __syncthreads();
        if (t == 0) flags[which] = ok;
    } else if (b == NB_SCAN + 2) {
        for (int i = t; i < N_GRAPHS * 96; i += 256) sums[i] = 0.f;
        if (t < N_GRAPHS) cnts[t] = 0;
    } else {
        int i = (b - (NB_SCAN + 3)) * 256 + t;
        if (i >= WTOT) return;
        const float* src; int K, off;
        if      (i < 8192)  { src = w10; K = 128; off = 0; }
        else if (i < 12288) { src = w20; K = 64;  off = 8192; }
        else if (i < 16384) { src = w11; K = 64;  off = 12288; }
        else if (i < 20480) { src = w21; K = 64;  off = 16384; }
        else if (i < 24576) { src = w12; K = 64;  off = 20480; }
        else                { src = w22; K = 64;  off = 24576; }
        int N = (i < 24576) ? 64 : 96;
        int local = i - off;
        int n = local / K, k = local % K;
        float v = src[k * N + n];
        __nv_bfloat16 h = __float2bfloat16(v);
        whi[i] = h;
        wlo[i] = __float2bfloat16(v - __bfloat162float(h));
    }
}

// ================= convert: deg histogram (from raw ei) + batch -> int32 =================
__global__ void convert_all_kernel(const void* ei, const void* batch, const int* flags,
                                   int* __restrict__ deg, int* __restrict__ b32) {
    int b = blockIdx.x, t = threadIdx.x;
    if (b < EB) {
        int i = b * 256 + t;
        if (i >= N_EDGES) return;
        int d;
        if (flags[0]) d = (int)((const long long*)ei)[N_EDGES + i];
        else          d = ((const int*)ei)[N_EDGES + i];
        atomicAdd(&deg[d], 1);
    } else {
        int i = (b - EB) * 256 + t;
        if (i >= N_NODES) return;
        if (flags[1]) b32[i] = (int)((const long long*)batch)[i];
        else          b32[i] = ((const int*)batch)[i];
    }
}

// ================= single-pass exclusive scan (decoupled lookback) =================
__global__ void scan_onepass_kernel(const int* __restrict__ deg,
                                    int* __restrict__ rowptr, int* __restrict__ cursor,
                                    unsigned long long* __restrict__ sstate) {
    __shared__ int sm[SCAN_BS];
    __shared__ int s_off;
    int b = blockIdx.x, t = threadIdx.x;
    int i = b * SCAN_BS + t;
    int v = (i < N_NODES) ? deg[i] : 0;
    sm[t] = v;
    __syncthreads();
    for (int off = 1; off < SCAN_BS; off <<= 1) {
        int x = (t >= off) ? sm[t - off] : 0;
        __syncthreads();
        sm[t] += x;
        __syncthreads();
    }
    int total = sm[SCAN_BS - 1];
    if (t == 0) {
        if (b == 0) {
            atomicExch(&sstate[0], (2ULL << 32) | (unsigned)total);
            s_off = 0;
        } else {
            atomicExch(&sstate[b], (1ULL << 32) | (unsigned)total);
            int run = 0;
            int j = b - 1;
            while (true) {
                unsigned long long w = atomicAdd(&sstate[j], 0ULL);
                unsigned st = (unsigned)(w >> 32);
                if (st == 0) { __nanosleep(40); continue; }
                run += (int)(w & 0xffffffffULL);
                if (st == 2) break;
                j--;
            }
            atomicExch(&sstate[b], (2ULL << 32) | (unsigned)(run + total));
            s_off = run;
        }
    }
    __syncthreads();
    int off0 = s_off;
    if (i < N_NODES) {
        int r = off0 + sm[t] - v;
        rowptr[i] = r;
        cursor[i] = r;
    }
    if (i == N_NODES - 1) rowptr[N_NODES] = off0 + sm[t];
}

// ================= fill: CSR column array from raw ei =================
__global__ void fill_kernel(const void* ei, const int* flags,
                            int* __restrict__ cursor, int* __restrict__ col) {
    int e = blockIdx.x * blockDim.x + threadIdx.x;
    if (e >= N_EDGES) return;
    int s, d;
    if (flags[0]) {
        const long long* p = (const long long*)ei;
        s = (int)p[e]; d = (int)p[N_EDGES + e];
    } else {
        const int* p = (const int*)ei;
        s = p[e]; d = p[N_EDGES + e];
    }
    int pos = atomicAdd(&cursor[d], 1);
    col[pos] = s;
}

// ================= standalone GEMM layer0: Y = X @ W1 (K=128, N=64), fp32 out =================
__global__ __launch_bounds__(128) void hgemm_l0(const float* __restrict__ X,
                                                const __nv_bfloat16* __restrict__ Whi,
                                                const __nv_bfloat16* __restrict__ Wlo,
                                                float* __restrict__ Y) {
    constexpr int K = 128, N = 64;
    constexpr int SP = K + 8, SPB = SP * 2, NT = N / 8;
    extern __shared__ char dsm[];
    uint32_t aHi = smem_u32(dsm);
    uint32_t aLo = aHi + 128 * SPB;
    uint32_t wHi = aLo + 128 * SPB;
    uint32_t wLo = wHi + N * SPB;

    const int tid = threadIdx.x, warp = tid >> 5, lane = tid & 31;
    const int base = blockIdx.x * 128;

    for (int i = tid; i < N * K / 2; i += 128) {
        int byte = i * 4;
        int row = byte / (K * 2), kb = byte - row * (K * 2);
        uint32_t off = (uint32_t)row * SPB + kb;
        sts32(wHi + off, ((const uint32_t*)Whi)[i]);
        sts32(wLo + off, ((const uint32_t*)Wlo)[i]);
    }
    constexpr int N4 = K / 4;
    for (int i = tid; i < 128 * N4; i += 128) {
        int row = i / N4, c4 = i - row * N4, col = c4 * 4;
        float4 v = make_float4(0.f, 0.f, 0.f, 0.f);
        if (base + row < N_NODES) v = ((const float4*)X)[(size_t)(base + row) * N4 + c4];
        uint32_t h01, l01, h23, l23;
        split2(v.x, v.y, h01, l01);
        split2(v.z, v.w, h23, l23);
        uint32_t off = (uint32_t)row * SPB + col * 2;
        sts32(aHi + off, h01); sts32(aHi + off + 4, h23);
        sts32(aLo + off, l01); sts32(aLo + off + 4, l23);
    }
    __syncthreads();

    float acc[2][NT][4];
#pragma unroll
    for (int t = 0; t < 2; t++)
#pragma unroll
        for (int n = 0; n < NT; n++)
#pragma unroll
            for (int j = 0; j < 4; j++) acc[t][n][j] = 0.f;

    const int arow = warp * 32 + (lane & 15);
    const int ahalf = lane >> 4;
    const int brow = lane & 7;
    const int bhalf = (lane >> 3) & 1;

#pragma unroll
    for (int s = 0; s < 3; s++) {
        uint32_t Ab = (s == 2) ? aLo : aHi;
        uint32_t Wb = (s == 1) ? wLo : wHi;
#pragma unroll
        for (int k16 = 0; k16 < K / 16; k16++) {
            uint32_t kbyte = (uint32_t)(k16 * 16) * 2;
            uint32_t af0[4], af1[4];
            ldsm4(af0, Ab + (uint32_t)arow * SPB + kbyte + ahalf * 16);
            ldsm4(af1, Ab + (uint32_t)(arow + 16) * SPB + kbyte + ahalf * 16);
#pragma unroll
            for (int n8 = 0; n8 < NT; n8++) {
                uint32_t bf[2];
                ldsm2(bf, Wb + (uint32_t)(n8 * 8 + brow) * SPB + kbyte + bhalf * 16);
                mma_bf16(acc[0][n8], af0, bf);
                mma_bf16(acc[1][n8], af1, bf);
            }
        }
    }
    const int r_in_warp = lane >> 2;
    const int cpair = (lane & 3) * 2;
#pragma unroll
    for (int t = 0; t < 2; t++) {
        int row0 = base + warp * 32 + t * 16 + r_in_warp;
        int row1 = row0 + 8;
#pragma unroll
        for (int n8 = 0; n8 < NT; n8++) {
            int col = n8 * 8 + cpair;
            if (row0 < N_NODES) *(float2*)(Y + (size_t)row0 * N + col) = make_float2(acc[t][n8][0], acc[t][n8][1]);
            if (row1 < N_NODES) *(float2*)(Y + (size_t)row1 * N + col) = make_float2(acc[t][n8][2], acc[t][n8][3]);
        }
    }
}

// ================= gather: AG = split(ReLU(gathersum + b1)) as bf16 hi/lo =================
__global__ __launch_bounds__(256) void gather_kernel(const float* __restrict__ Y,
                                                     const int* __restrict__ rowptr,
                                                     const int* __restrict__ col,
                                                     const float* __restrict__ b1,
                                                     __nv_bfloat16* __restrict__ AGhi,
                                                     __nv_bfloat16* __restrict__ AGlo) {
    int w = (blockIdx.x * blockDim.x + threadIdx.x) >> 5;
    int lane = threadIdx.x & 31;
    if (w >= N_NODES) return;
    const float2* y2 = (const float2*)Y;
    float2 bias = ((const float2*)b1)[lane];
    int r0 = rowptr[w], r1 = rowptr[w + 1];
    float2 acc = y2[(size_t)w * 32 + lane];
    int e = r0;
    for (; e + 3 < r1; e += 4) {
        int s0 = col[e], s1 = col[e + 1], s2 = col[e + 2], s3 = col[e + 3];
        float2 a = y2[(size_t)s0 * 32 + lane];
        float2 b = y2[(size_t)s1 * 32 + lane];
        float2 c = y2[(size_t)s2 * 32 + lane];
        float2 d = y2[(size_t)s3 * 32 + lane];
        acc.x += (a.x + b.x) + (c.x + d.x);
        acc.y += (a.y + b.y) + (c.y + d.y);
    }
    if (e + 1 < r1) {
        int s0 = col[e], s1 = col[e + 1];
        float2 a = y2[(size_t)s0 * 32 + lane];
        float2 b = y2[(size_t)s1 * 32 + lane];
        acc.x += a.x + b.x;
        acc.y += a.y + b.y;
        e += 2;
    }
    if (e < r1) {
        int s = col[e];
        float2 a = y2[(size_t)s * 32 + lane];
        acc.x += a.x;
        acc.y += a.y;
    }
    acc.x = fmaxf(acc.x + bias.x, 0.f);
    acc.y = fmaxf(acc.y + bias.y, 0.f);
    uint32_t hi, lo;
    split2(acc.x, acc.y, hi, lo);
    ((uint32_t*)AGhi)[(size_t)w * 32 + lane] = hi;
    ((uint32_t*)AGlo)[(size_t)w * 32 + lane] = lo;
}

// ================= fused MLP: AG(bf16) @ W2 -> BN+ReLU -> [@W1next -> Y | out] =================
template <int NOUT, bool CHAIN>
__global__ __launch_bounds__(128) void fused_mlp(const __nv_bfloat16* __restrict__ AGhi,
                                                 const __nv_bfloat16* __restrict__ AGlo,
                                                 const __nv_bfloat16* __restrict__ W2hi,
                                                 const __nv_bfloat16* __restrict__ W2lo,
                                                 const float* __restrict__ b2,
                                                 const float* __restrict__ bng,
                                                 const float* __restrict__ bnb,
                                                 const float* __restrict__ bnm,
                                                 const float* __restrict__ bnv,
                                                 const __nv_bfloat16* __restrict__ W1hi,
                                                 const __nv_bfloat16* __restrict__ W1lo,
                                                 float* __restrict__ OUT) {
    constexpr int K = 64;
    constexpr int SP = K + 8, SPB = SP * 2;
    constexpr int NT = NOUT / 8;
    extern __shared__ char dsm[];
    uint32_t aHi = smem_u32(dsm);
    uint32_t aLo = aHi + 128 * SPB;
    uint32_t wHi = aLo + 128 * SPB;
    uint32_t wLo = wHi + NOUT * SPB;
    __shared__ float sScale[NOUT];
    __shared__ float sShift[NOUT];

    const int tid = threadIdx.x, warp = tid >> 5, lane = tid & 31;
    const int base = blockIdx.x * 128;

    if (tid < NOUT) {
        float s = bng[tid] * rsqrtf(bnv[tid] + BN_EPS);
        sScale[tid] = s;
        sShift[tid] = (b2[tid] - bnm[tid]) * s + bnb[tid];
    }
    for (int i = tid; i < NOUT * K / 2; i += 128) {
        int byte = i * 4;
        int row = byte >> 7, kb = byte & 127;
        uint32_t off = (uint32_t)row * SPB + kb;
        sts32(wHi + off, ((const uint32_t*)W2hi)[i]);
        sts32(wLo + off, ((const uint32_t*)W2lo)[i]);
    }
    for (int i = tid; i < 128 * 32; i += 128) {
        int row = i >> 5, w = i & 31;
        uint32_t h = 0, l = 0;
        if (base + row < N_NODES) {
            h = ((const uint32_t*)AGhi)[(size_t)(base + row) * 32 + w];
            l = ((const uint32_t*)AGlo)[(size_t)(base + row) * 32 + w];
        }
        uint32_t off = (uint32_t)row * SPB + w * 4;
        sts32(aHi + off, h);
        sts32(aLo + off, l);
    }
    __syncthreads();

    float acc[2][NT][4];
#pragma unroll
    for (int t = 0; t < 2; t++)
#pragma unroll
        for (int n = 0; n < NT; n++)
#pragma unroll
            for (int j = 0; j < 4; j++) acc[t][n][j] = 0.f;

    const int arow = warp * 32 + (lane & 15);
    const int ahalf = lane >> 4;
    const int brow = lane & 7;
    const int bhalf = (lane >> 3) & 1;

#pragma unroll
    for (int s = 0; s < 3; s++) {
        uint32_t Ab = (s == 2) ? aLo : aHi;
        uint32_t Wb = (s == 1) ? wLo : wHi;
#pragma unroll
        for (int k16 = 0; k16 < 4; k16++) {
            uint32_t kbyte = (uint32_t)(k16 * 32);
            uint32_t af0[4], af1[4];
            ldsm4(af0, Ab + (uint32_t)arow * SPB + kbyte + ahalf * 16);
            ldsm4(af1, Ab + (uint32_t)(arow + 16) * SPB + kbyte + ahalf * 16);
#pragma unroll
            for (int n8 = 0; n8 < NT; n8++) {
                uint32_t bf[2];
                ldsm2(bf, Wb + (uint32_t)(n8 * 8 + brow) * SPB + kbyte + bhalf * 16);
                mma_bf16(acc[0][n8], af0, bf);
                mma_bf16(acc[1][n8], af1, bf);
            }
        }
    }

    const int r_in_warp = lane >> 2;
    const int cpair = (lane & 3) * 2;
#pragma unroll
    for (int t = 0; t < 2; t++) {
#pragma unroll
        for (int n8 = 0; n8 < NT; n8++) {
            int c = n8 * 8 + cpair;
            acc[t][n8][0] = fmaxf(acc[t][n8][0] * sScale[c] + sShift[c], 0.f);
            acc[t][n8][1] = fmaxf(acc[t][n8][1] * sScale[c + 1] + sShift[c + 1], 0.f);
            acc[t][n8][2] = fmaxf(acc[t][n8][2] * sScale[c] + sShift[c], 0.f);
            acc[t][n8][3] = fmaxf(acc[t][n8][3] * sScale[c + 1] + sShift[c + 1], 0.f);
        }
    }

    if (!CHAIN) {
#pragma unroll
        for (int t = 0; t < 2; t++) {
            int row0 = base + warp * 32 + t * 16 + r_in_warp;
            int row1 = row0 + 8;
#pragma unroll
            for (int n8 = 0; n8 < NT; n8++) {
                int c = n8 * 8 + cpair;
                if (row0 < N_NODES) *(float2*)(OUT + (size_t)row0 * NOUT + c) = make_float2(acc[t][n8][0], acc[t][n8][1]);
                if (row1 < N_NODES) *(float2*)(OUT + (size_t)row1 * NOUT + c) = make_float2(acc[t][n8][2], acc[t][n8][3]);
            }
        }
        return;
    }

    // ---- chained next-layer GEMM1: y_next = a @ W1next (fp32 out) ----
    __syncthreads();
#pragma unroll
    for (int t = 0; t < 2; t++) {
        int rl0 = warp * 32 + t * 16 + r_in_warp;
        int rl1 = rl0 + 8;
#pragma unroll
        for (int n8 = 0; n8 < NT; n8++) {
            int cb = (n8 * 8 + cpair) * 2;
            uint32_t h, l;
            split2(acc[t][n8][0], acc[t][n8][1], h, l);
            sts32(aHi + (uint32_t)rl0 * SPB + cb, h);
            sts32(aLo + (uint32_t)rl0 * SPB + cb, l);
            split2(acc[t][n8][2], acc[t][n8][3], h, l);
            sts32(aHi + (uint32_t)rl1 * SPB + cb, h);
            sts32(aLo + (uint32_t)rl1 * SPB + cb, l);
        }
    }
    for (int i = tid; i < 64 * K / 2; i += 128) {
        int byte = i * 4;
        int row = byte >> 7, kb = byte & 127;
        uint32_t off = (uint32_t)row * SPB + kb;
        sts32(wHi + off, ((const uint32_t*)W1hi)[i]);
        sts32(wLo + off, ((const uint32_t*)W1lo)[i]);
    }
    __syncthreads();

    float acc2[2][8][4];
#pragma unroll
    for (int t = 0; t < 2; t++)
#pragma unroll
        for (int n = 0; n < 8; n++)
#pragma unroll
            for (int j = 0; j < 4; j++) acc2[t][n][j] = 0.f;

#pragma unroll
    for (int s = 0; s < 3; s++) {
        uint32_t Ab = (s == 2) ? aLo : aHi;
        uint32_t Wb = (s == 1) ? wLo : wHi;
#pragma unroll
        for (int k16 = 0; k16 < 4; k16++) {
            uint32_t kbyte = (uint32_t)(k16 * 32);
            uint32_t af0[4], af1[4];
            ldsm4(af0, Ab + (uint32_t)arow * SPB + kbyte + ahalf * 16);
            ldsm4(af1, Ab + (uint32_t)(arow + 16) * SPB + kbyte + ahalf * 16);
#pragma unroll
            for (int n8 = 0; n8 < 8; n8++) {
                uint32_t bf[2];
                ldsm2(bf, Wb + (uint32_t)(n8 * 8 + brow) * SPB + kbyte + bhalf * 16);
                mma_bf16(acc2[0][n8], af0, bf);
                mma_bf16(acc2[1][n8], af1, bf);
            }
        }
    }
#pragma unroll
    for (int t = 0; t < 2; t++) {
        int row0 = base + warp * 32 + t * 16 + r_in_warp;
        int row1 = row0 + 8;
#pragma unroll
        for (int n8 = 0; n8 < 8; n8++) {
            int c = n8 * 8 + cpair;
            if (row0 < N_NODES) *(float2*)(OUT + (size_t)row0 * 64 + c) = make_float2(acc2[t][n8][0], acc2[t][n8][1]);
            if (row1 < N_NODES) *(float2*)(OUT + (size_t)row1 * 64 + c) = make_float2(acc2[t][n8][2], acc2[t][n8][3]);
        }
    }
}

// ================= pool =================
#define PB_NODES 64
__global__ void pool_kernel(const float* __restrict__ F, const int* __restrict__ batch,
                            float* __restrict__ sums, int* __restrict__ cnts) {
    __shared__ int sb[PB_NODES];
    const int start = blockIdx.x * PB_NODES;
    const int nn = min(PB_NODES, N_NODES - start);
    const int tid = threadIdx.x;   // 96
    if (tid < nn) sb[tid] = batch[start + tid];
    __syncthreads();
    if (tid == 0) {
        int cur = sb[0], c = 0;
        for (int n = 0; n < nn; n++) {
            int g = sb[n];
            if (g != cur) { atomicAdd(&cnts[cur], c); cur = g; c = 0; }
            c++;
        }
        atomicAdd(&cnts[cur], c);
    }
    int cur = sb[0];
    float acc = 0.f;
    for (int n = 0; n < nn; n++) {
        int g = sb[n];
        float v = F[(size_t)(start + n) * 96 + tid];
        if (g != cur) { atomicAdd(&sums[cur * 96 + tid], acc); acc = 0.f; cur = g; }
        acc += v;
    }
    atomicAdd(&sums[cur * 96 + tid], acc);
}
__global__ void finalize_kernel(const float* __restrict__ sums, const int* __restrict__ cnts,
                                float* __restrict__ out) {
    int i = blockIdx.x * blockDim.x + threadIdx.x;
    if (i >= N_GRAPHS * 96) return;
    float c = fmaxf((float)cnts[i / 96], 1.f);
    out[i] = sums[i] / c;
}

// ================= launch =================
extern "C" void kernel_launch(void* const* d_in, const int* in_sizes, int n_in,
                              void* d_out, int out_size) {
    const float* x     = (const float*)d_in[0];
    const void*  ei    = d_in[1];
    const void*  batch = d_in[2];
    const float* P[24];
    for (int i = 0; i < 24; i++) P[i] = (const float*)d_in[3 + i];

    float *y, *f, *sums;
    __nv_bfloat16 *aghi, *aglo, *whi, *wlo;
    int *cnts, *b32, *flags;
    int *deg, *rowptr, *cursor, *colv;
    unsigned long long* sstate;
    cudaGetSymbolAddress((void**)&y,      g_y);
    cudaGetSymbolAddress((void**)&aghi,   g_aghi);
    cudaGetSymbolAddress((void**)&aglo,   g_aglo);
    cudaGetSymbolAddress((void**)&f,      g_f);
    cudaGetSymbolAddress((void**)&sums,   g_sums);
    cudaGetSymbolAddress((void**)&cnts,   g_cnts);
    cudaGetSymbolAddress((void**)&b32,    g_batch32);
    cudaGetSymbolAddress((void**)&flags,  g_flags);
    cudaGetSymbolAddress((void**)&deg,    g_deg);
    cudaGetSymbolAddress((void**)&rowptr, g_rowptr);
    cudaGetSymbolAddress((void**)&cursor, g_cursor);
    cudaGetSymbolAddress((void**)&colv,   g_col);
    cudaGetSymbolAddress((void**)&sstate, g_scanstate);
    cudaGetSymbolAddress((void**)&whi,    g_whi);
    cudaGetSymbolAddress((void**)&wlo,    g_wlo);

    const int SM_L0  = (256 + 128) * (136 * 2);   // 104448
    const int SM_F64 = (256 + 128) * (72 * 2);    // 55296
    const int SM_F96 = (256 + 192) * (72 * 2);    // 64512
    cudaFuncSetAttribute((const void*)hgemm_l0, cudaFuncAttributeMaxDynamicSharedMemorySize, SM_L0);
    cudaFuncSetAttribute((const void*)fused_mlp<64, true>,  cudaFuncAttributeMaxDynamicSharedMemorySize, SM_F64);
    cudaFuncSetAttribute((const void*)fused_mlp<96, false>, cudaFuncAttributeMaxDynamicSharedMemorySize, SM_F96);

    const int NB = (N_NODES + 127) / 128;          // 782
    const int GB = (N_NODES * 32 + 255) / 256;     // 12500
    const int PREP_B = NB_SCAN + 3 + WB;           // 514

    prep_kernel<<<PREP_B, 256>>>(ei, batch, flags, deg, sums, cnts, sstate,
                                 P[0], P[2], P[8], P[10], P[16], P[18], whi, wlo);
    convert_all_kernel<<<EB + NB_SCAN, 256>>>(ei, batch, flags, deg, b32);
    scan_onepass_kernel<<<NB_SCAN, SCAN_BS>>>(deg, rowptr, cursor, sstate);
    fill_kernel<<<EB, 256>>>(ei, flags, cursor, colv);

    const int O_W10 = 0, O_W20 = 8192, O_W11 = 12288, O_W21 = 16384, O_W12 = 20480, O_W22 = 24576;

    hgemm_l0<<<NB, 128, SM_L0>>>(x, whi + O_W10, wlo + O_W10, y);
    gather_kernel<<<GB, 256>>>(y, rowptr, colv, P[1], aghi, aglo);
    fused_mlp<64, true><<<NB, 128, SM_F64>>>(aghi, aglo, whi + O_W20, wlo + O_W20,
                                             P[3], P[4], P[5], P[6], P[7],
                                             whi + O_W11, wlo + O_W11, y);
    gather_kernel<<<GB, 256>>>(y, rowptr, colv, P[9], aghi, aglo);
    fused_mlp<64, true><<<NB, 128, SM_F64>>>(aghi, aglo, whi + O_W21, wlo + O_W21,
                                             P[11], P[12], P[13], P[14], P[15],
                                             whi + O_W12, wlo + O_W12, y);
    gather_kernel<<<GB, 256>>>(y, rowptr, colv, P[17], aghi, aglo);
    fused_mlp<96, false><<<NB, 128, SM_F96>>>(aghi, aglo, whi + O_W22, wlo + O_W22,
                                              P[19], P[20], P[21], P[22], P[23],
                                              nullptr, nullptr, f);

    pool_kernel<<<(N_NODES + PB_NODES - 1) / PB_NODES, 96>>>(f, b32, sums, cnts);
    finalize_kernel<<<(N_GRAPHS * 96 + 255) / 256, 256>>>(sums, cnts, (float*)d_out);
}

// round 12
// speedup vs baseline: 1.6530x; 1.0422x over previous
#include <cuda_runtime.h>
#include <cuda_bf16.h>
#include <cstdint>

#define N_NODES 100000
#define N_EDGES 600000
#define N_GRAPHS 64
#define BN_EPS 1e-5f
#define SCAN_BS 256
#define NB_SCAN ((N_NODES + SCAN_BS - 1) / SCAN_BS)   // 391
#define EB ((N_EDGES + 255) / 256)                     // 2344
#define WTOT 30720
#define WB ((WTOT + 255) / 256)                        // 120

// ================= helpers =================
__device__ __forceinline__ uint32_t smem_u32(const void* p) {
    uint32_t a;
    asm("{ .reg .u64 t; cvta.to.shared.u64 t, %1; cvt.u32.u64 %0, t; }" : "=r"(a) : "l"(p));
    return a;
}
__device__ __forceinline__ void sts32(uint32_t addr, uint32_t v) {
    asm volatile("st.shared.b32 [%0], %1;" :: "r"(addr), "r"(v));
}
__device__ __forceinline__ void ldsm4(uint32_t r[4], uint32_t a) {
    asm volatile("ldmatrix.sync.aligned.m8n8.x4.shared.b16 {%0,%1,%2,%3}, [%4];"
                 : "=r"(r[0]), "=r"(r[1]), "=r"(r[2]), "=r"(r[3]) : "r"(a));
}
__device__ __forceinline__ void ldsm2(uint32_t r[2], uint32_t a) {
    asm volatile("ldmatrix.sync.aligned.m8n8.x2.shared.b16 {%0,%1}, [%2];"
                 : "=r"(r[0]), "=r"(r[1]) : "r"(a));
}
__device__ __forceinline__ void mma_bf16(float c[4], const uint32_t a[4], const uint32_t b[2]) {
    asm volatile("mma.sync.aligned.m16n8k16.row.col.f32.bf16.bf16.f32 "
                 "{%0,%1,%2,%3}, {%4,%5,%6,%7}, {%8,%9}, {%0,%1,%2,%3};"
                 : "+f"(c[0]), "+f"(c[1]), "+f"(c[2]), "+f"(c[3])
                 : "r"(a[0]), "r"(a[1]), "r"(a[2]), "r"(a[3]), "r"(b[0]), "r"(b[1]));
}
__device__ __forceinline__ void split2(float a, float b, uint32_t& hi, uint32_t& lo) {
    __nv_bfloat16 ha = __float2bfloat16(a), hb = __float2bfloat16(b);
    __nv_bfloat16 la = __float2bfloat16(a - __bfloat162float(ha));
    __nv_bfloat16 lb = __float2bfloat16(b - __bfloat162float(hb));
    __nv_bfloat162 H; H.x = ha; H.y = hb;
    __nv_bfloat162 L; L.x = la; L.y = lb;
    hi = *(uint32_t*)&H; lo = *(uint32_t*)&L;
}

// ================= scratch =================
__device__ float g_y[(size_t)N_NODES * 64];
__device__ __nv_bfloat16 g_aghi[(size_t)N_NODES * 64];
__device__ __nv_bfloat16 g_aglo[(size_t)N_NODES * 64];
__device__ float g_f[(size_t)N_NODES * 96];
__device__ float g_sums[N_GRAPHS * 96];
__device__ int   g_cnts[N_GRAPHS];
__device__ int   g_batch32[N_NODES];
__device__ int   g_deg[N_NODES];
__device__ int   g_rowptr[N_NODES + 1];
__device__ int   g_cursor[N_NODES];
__device__ int   g_col[N_EDGES];
__device__ unsigned long long g_scanstate[NB_SCAN];
__device__ int   g_flags[2];
__device__ __nv_bfloat16 g_whi[WTOT];
__device__ __nv_bfloat16 g_wlo[WTOT];

// ================= graph-side prep: detect dtypes + zero deg/sums/cnts/scanstate =================
__global__ void prep_graph_kernel(const void* ei, const void* batch, int* flags,
                                  int* __restrict__ deg, float* __restrict__ sums,
                                  int* __restrict__ cnts,
                                  unsigned long long* __restrict__ sstate) {
    int b = blockIdx.x, t = threadIdx.x;
    if (b < NB_SCAN) {
        int i = b * 256 + t;
        if (i < N_NODES) deg[i] = 0;
        if (t == 0) sstate[b] = 0ULL;
    } else if (b == NB_SCAN || b == NB_SCAN + 1) {
        __shared__ int ok;
        if (t == 0) ok = 1;
        __syncthreads();
        int which = b - NB_SCAN;
        const void* p = (which == 0) ? ei : batch;
        long long n64_max = (which == 0) ? (long long)N_EDGES : (long long)N_NODES / 2;
        int maxval = (which == 0) ? N_NODES : N_GRAPHS;
        long long idx = (long long)t * (n64_max - 1) / 255;
        long long v = ((const long long*)p)[idx];
        if (v < 0 || v >= maxval) atomicAnd(&ok, 0);
        __syncthreads();
        if (t == 0) flags[which] = ok;
    } else {
        for (int i = t; i < N_GRAPHS * 96; i += 256) sums[i] = 0.f;
        if (t < N_GRAPHS) cnts[t] = 0;
    }
}

// ================= weight split (independent branch) =================
__global__ void wsplit_kernel(const float* w10, const float* w20, const float* w11,
                              const float* w21, const float* w12, const float* w22,
                              __nv_bfloat16* __restrict__ whi, __nv_bfloat16* __restrict__ wlo) {
    int i = blockIdx.x * blockDim.x + threadIdx.x;
    if (i >= WTOT) return;
    const float* src; int K, off;
    if      (i < 8192)  { src = w10; K = 128; off = 0; }
    else if (i < 12288) { src = w20; K = 64;  off = 8192; }
    else if (i < 16384) { src = w11; K = 64;  off = 12288; }
    else if (i < 20480) { src = w21; K = 64;  off = 16384; }
    else if (i < 24576) { src = w12; K = 64;  off = 20480; }
    else                { src = w22; K = 64;  off = 24576; }
    int N = (i < 24576) ? 64 : 96;
    int local = i - off;
    int n = local / K, k = local % K;
    float v = src[k * N + n];
    __nv_bfloat16 h = __float2bfloat16(v);
    whi[i] = h;
    wlo[i] = __float2bfloat16(v - __bfloat162float(h));
}

// ================= convert: deg histogram (from raw ei) + batch -> int32 =================
__global__ void convert_all_kernel(const void* ei, const void* batch, const int* flags,
                                   int* __restrict__ deg, int* __restrict__ b32) {
    int b = blockIdx.x, t = threadIdx.x;
    if (b < EB) {
        int i = b * 256 + t;
        if (i >= N_EDGES) return;
        int d;
        if (flags[0]) d = (int)((const long long*)ei)[N_EDGES + i];
        else          d = ((const int*)ei)[N_EDGES + i];
        atomicAdd(&deg[d], 1);
    } else {
        int i = (b - EB) * 256 + t;
        if (i >= N_NODES) return;
        if (flags[1]) b32[i] = (int)((const long long*)batch)[i];
        else          b32[i] = ((const int*)batch)[i];
    }
}

// ================= single-pass exclusive scan (decoupled lookback) =================
__global__ void scan_onepass_kernel(const int* __restrict__ deg,
                                    int* __restrict__ rowptr, int* __restrict__ cursor,
                                    unsigned long long* __restrict__ sstate) {
    __shared__ int sm[SCAN_BS];
    __shared__ int s_off;
    int b = blockIdx.x, t = threadIdx.x;
    int i = b * SCAN_BS + t;
    int v = (i < N_NODES) ? deg[i] : 0;
    sm[t] = v;
    __syncthreads();
    for (int off = 1; off < SCAN_BS; off <<= 1) {
        int x = (t >= off) ? sm[t - off] : 0;
        __syncthreads();
        sm[t] += x;
        __syncthreads();
    }
    int total = sm[SCAN_BS - 1];
    if (t == 0) {
        if (b == 0) {
            atomicExch(&sstate[0], (2ULL << 32) | (unsigned)total);
            s_off = 0;
        } else {
            atomicExch(&sstate[b], (1ULL << 32) | (unsigned)total);
            int run = 0;
            int j = b - 1;
            while (true) {
                unsigned long long w = atomicAdd(&sstate[j], 0ULL);
                unsigned st = (unsigned)(w >> 32);
                if (st == 0) { __nanosleep(40); continue; }
                run += (int)(w & 0xffffffffULL);
                if (st == 2) break;
                j--;
            }
            atomicExch(&sstate[b], (2ULL << 32) | (unsigned)(run + total));
            s_off = run;
        }
    }
    __syncthreads();
    int off0 = s_off;
    if (i < N_NODES) {
        int r = off0 + sm[t] - v;
        rowptr[i] = r;
        cursor[i] = r;
    }
    if (i == N_NODES - 1) rowptr[N_NODES] = off0 + sm[t];
}

// ================= fill: CSR column array from raw ei =================
__global__ void fill_kernel(const void* ei, const int* flags,
                            int* __restrict__ cursor, int* __restrict__ col) {
    int e = blockIdx.x * blockDim.x + threadIdx.x;
    if (e >= N_EDGES) return;
    int s, d;
    if (flags[0]) {
        const long long* p = (const long long*)ei;
        s = (int)p[e]; d = (int)p[N_EDGES + e];
    } else {
        const int* p = (const int*)ei;
        s = p[e]; d = p[N_EDGES + e];
    }
    int pos = atomicAdd(&cursor[d], 1);
    col[pos] = s;
}

// ================= standalone GEMM layer0: Y = X @ W1 (K=128, N=64), fp32 out =================
__global__ __launch_bounds__(128) void hgemm_l0(const float* __restrict__ X,
                                                const __nv_bfloat16* __restrict__ Whi,
                                                const __nv_bfloat16* __restrict__ Wlo,
                                                float* __restrict__ Y) {
    constexpr int K = 128, N = 64;
    constexpr int SP = K + 8, SPB = SP * 2, NT = N / 8;
    extern __shared__ char dsm[];
    uint32_t aHi = smem_u32(dsm);
    uint32_t aLo = aHi + 128 * SPB;
    uint32_t wHi = aLo + 128 * SPB;
    uint32_t wLo = wHi + N * SPB;

    const int tid = threadIdx.x, warp = tid >> 5, lane = tid & 31;
    const int base = blockIdx.x * 128;

    for (int i = tid; i < N * K / 2; i += 128) {
        int byte = i * 4;
        int row = byte / (K * 2), kb = byte - row * (K * 2);
        uint32_t off = (uint32_t)row * SPB + kb;
        sts32(wHi + off, ((const uint32_t*)Whi)[i]);
        sts32(wLo + off, ((const uint32_t*)Wlo)[i]);
    }
    constexpr int N4 = K / 4;
    for (int i = tid; i < 128 * N4; i += 128) {
        int row = i / N4, c4 = i - row * N4, col = c4 * 4;
        float4 v = make_float4(0.f, 0.f, 0.f, 0.f);
        if (base + row < N_NODES) v = ((const float4*)X)[(size_t)(base + row) * N4 + c4];
        uint32_t h01, l01, h23, l23;
        split2(v.x, v.y, h01, l01);
        split2(v.z, v.w, h23, l23);
        uint32_t off = (uint32_t)row * SPB + col * 2;
        sts32(aHi + off, h01); sts32(aHi + off + 4, h23);
        sts32(aLo + off, l01); sts32(aLo + off + 4, l23);
    }
    __syncthreads();

    float acc[2][NT][4];
#pragma unroll
    for (int t = 0; t < 2; t++)
#pragma unroll
        for (int n = 0; n < NT; n++)
#pragma unroll
            for (int j = 0; j < 4; j++) acc[t][n][j] = 0.f;

    const int arow = warp * 32 + (lane & 15);
    const int ahalf = lane >> 4;
    const int brow = lane & 7;
    const int bhalf = (lane >> 3) & 1;

#pragma unroll
    for (int s = 0; s < 3; s++) {
        uint32_t Ab = (s == 2) ? aLo : aHi;
        uint32_t Wb = (s == 1) ? wLo : wHi;
#pragma unroll
        for (int k16 = 0; k16 < K / 16; k16++) {
            uint32_t kbyte = (uint32_t)(k16 * 16) * 2;
            uint32_t af0[4], af1[4];
            ldsm4(af0, Ab + (uint32_t)arow * SPB + kbyte + ahalf * 16);
            ldsm4(af1, Ab + (uint32_t)(arow + 16) * SPB + kbyte + ahalf * 16);
#pragma unroll
            for (int n8 = 0; n8 < NT; n8++) {
                uint32_t bf[2];
                ldsm2(bf, Wb + (uint32_t)(n8 * 8 + brow) * SPB + kbyte + bhalf * 16);
                mma_bf16(acc[0][n8], af0, bf);
                mma_bf16(acc[1][n8], af1, bf);
            }
        }
    }
    const int r_in_warp = lane >> 2;
    const int cpair = (lane & 3) * 2;
#pragma unroll
    for (int t = 0; t < 2; t++) {
        int row0 = base + warp * 32 + t * 16 + r_in_warp;
        int row1 = row0 + 8;
#pragma unroll
        for (int n8 = 0; n8 < NT; n8++) {
            int col = n8 * 8 + cpair;
            if (row0 < N_NODES) *(float2*)(Y + (size_t)row0 * N + col) = make_float2(acc[t][n8][0], acc[t][n8][1]);
            if (row1 < N_NODES) *(float2*)(Y + (size_t)row1 * N + col) = make_float2(acc[t][n8][2], acc[t][n8][3]);
        }
    }
}

// ================= gather: AG = split(ReLU(gathersum + b1)) as bf16 hi/lo =================
__global__ __launch_bounds__(256) void gather_kernel(const float* __restrict__ Y,
                                                     const int* __restrict__ rowptr,
                                                     const int* __restrict__ col,
                                                     const float* __restrict__ b1,
                                                     __nv_bfloat16* __restrict__ AGhi,
                                                     __nv_bfloat16* __restrict__ AGlo) {
    int w = (blockIdx.x * blockDim.x + threadIdx.x) >> 5;
    int lane = threadIdx.x & 31;
    if (w >= N_NODES) return;
    const float2* y2 = (const float2*)Y;
    float2 bias = ((const float2*)b1)[lane];
    int r0 = rowptr[w], r1 = rowptr[w + 1];
    float2 acc = y2[(size_t)w * 32 + lane];
    int e = r0;
    for (; e + 3 < r1; e += 4) {
        int s0 = col[e], s1 = col[e + 1], s2 = col[e + 2], s3 = col[e + 3];
        float2 a = y2[(size_t)s0 * 32 + lane];
        float2 b = y2[(size_t)s1 * 32 + lane];
        float2 c = y2[(size_t)s2 * 32 + lane];
        float2 d = y2[(size_t)s3 * 32 + lane];
        acc.x += (a.x + b.x) + (c.x + d.x);
        acc.y += (a.y + b.y) + (c.y + d.y);
    }
    if (e + 1 < r1) {
        int s0 = col[e], s1 = col[e + 1];
        float2 a = y2[(size_t)s0 * 32 + lane];
        float2 b = y2[(size_t)s1 * 32 + lane];
        acc.x += a.x + b.x;
        acc.y += a.y + b.y;
        e += 2;
    }
    if (e < r1) {
        int s = col[e];
        float2 a = y2[(size_t)s * 32 + lane];
        acc.x += a.x;
        acc.y += a.y;
    }
    acc.x = fmaxf(acc.x + bias.x, 0.f);
    acc.y = fmaxf(acc.y + bias.y, 0.f);
    uint32_t hi, lo;
    split2(acc.x, acc.y, hi, lo);
    ((uint32_t*)AGhi)[(size_t)w * 32 + lane] = hi;
    ((uint32_t*)AGlo)[(size_t)w * 32 + lane] = lo;
}

// ================= fused MLP: AG(bf16) @ W2 -> BN+ReLU -> [@W1next -> Y | out] =================
template <int NOUT, bool CHAIN>
__global__ __launch_bounds__(128) void fused_mlp(const __nv_bfloat16* __restrict__ AGhi,
                                                 const __nv_bfloat16* __restrict__ AGlo,
                                                 const __nv_bfloat16* __restrict__ W2hi,
                                                 const __nv_bfloat16* __restrict__ W2lo,
                                                 const float* __restrict__ b2,
                                                 const float* __restrict__ bng,
                                                 const float* __restrict__ bnb,
                                                 const float* __restrict__ bnm,
                                                 const float* __restrict__ bnv,
                                                 const __nv_bfloat16* __restrict__ W1hi,
                                                 const __nv_bfloat16* __restrict__ W1lo,
                                                 float* __restrict__ OUT) {
    constexpr int K = 64;
    constexpr int SP = K + 8, SPB = SP * 2;
    constexpr int NT = NOUT / 8;
    extern __shared__ char dsm[];
    uint32_t aHi = smem_u32(dsm);
    uint32_t aLo = aHi + 128 * SPB;
    uint32_t wHi = aLo + 128 * SPB;
    uint32_t wLo = wHi + NOUT * SPB;
    __shared__ float sScale[NOUT];
    __shared__ float sShift[NOUT];

    const int tid = threadIdx.x, warp = tid >> 5, lane = tid & 31;
    const int base = blockIdx.x * 128;

    if (tid < NOUT) {
        float s = bng[tid] * rsqrtf(bnv[tid] + BN_EPS);
        sScale[tid] = s;
        sShift[tid] = (b2[tid] - bnm[tid]) * s + bnb[tid];
    }
    for (int i = tid; i < NOUT * K / 2; i += 128) {
        int byte = i * 4;
        int row = byte >> 7, kb = byte & 127;
        uint32_t off = (uint32_t)row * SPB + kb;
        sts32(wHi + off, ((const uint32_t*)W2hi)[i]);
        sts32(wLo + off, ((const uint32_t*)W2lo)[i]);
    }
    for (int i = tid; i < 128 * 32; i += 128) {
        int row = i >> 5, w = i & 31;
        uint32_t h = 0, l = 0;
        if (base + row < N_NODES) {
            h = ((const uint32_t*)AGhi)[(size_t)(base + row) * 32 + w];
            l = ((const uint32_t*)AGlo)[(size_t)(base + row) * 32 + w];
        }
        uint32_t off = (uint32_t)row * SPB + w * 4;
        sts32(aHi + off, h);
        sts32(aLo + off, l);
    }
    __syncthreads();

    float acc[2][NT][4];
#pragma unroll
    for (int t = 0; t < 2; t++)
#pragma unroll
        for (int n = 0; n < NT; n++)
#pragma unroll
            for (int j = 0; j < 4; j++) acc[t][n][j] = 0.f;

    const int arow = warp * 32 + (lane & 15);
    const int ahalf = lane >> 4;
    const int brow = lane & 7;
    const int bhalf = (lane >> 3) & 1;

#pragma unroll
    for (int s = 0; s < 3; s++) {
        uint32_t Ab = (s == 2) ? aLo : aHi;
        uint32_t Wb = (s == 1) ? wLo : wHi;
#pragma unroll
        for (int k16 = 0; k16 < 4; k16++) {
            uint32_t kbyte = (uint32_t)(k16 * 32);
            uint32_t af0[4], af1[4];
            ldsm4(af0, Ab + (uint32_t)arow * SPB + kbyte + ahalf * 16);
            ldsm4(af1, Ab + (uint32_t)(arow + 16) * SPB + kbyte + ahalf * 16);
#pragma unroll
            for (int n8 = 0; n8 < NT; n8++) {
                uint32_t bf[2];
                ldsm2(bf, Wb + (uint32_t)(n8 * 8 + brow) * SPB + kbyte + bhalf * 16);
                mma_bf16(acc[0][n8], af0, bf);
                mma_bf16(acc[1][n8], af1, bf);
            }
        }
    }

    const int r_in_warp = lane >> 2;
    const int cpair = (lane & 3) * 2;
#pragma unroll
    for (int t = 0; t < 2; t++) {
#pragma unroll
        for (int n8 = 0; n8 < NT; n8++) {
            int c = n8 * 8 + cpair;
            acc[t][n8][0] = fmaxf(acc[t][n8][0] * sScale[c] + sShift[c], 0.f);
            acc[t][n8][1] = fmaxf(acc[t][n8][1] * sScale[c + 1] + sShift[c + 1], 0.f);
            acc[t][n8][2] = fmaxf(acc[t][n8][2] * sScale[c] + sShift[c], 0.f);
            acc[t][n8][3] = fmaxf(acc[t][n8][3] * sScale[c + 1] + sShift[c + 1], 0.f);
        }
    }

    if (!CHAIN) {
#pragma unroll
        for (int t = 0; t < 2; t++) {
            int row0 = base + warp * 32 + t * 16 + r_in_warp;
            int row1 = row0 + 8;
#pragma unroll
            for (int n8 = 0; n8 < NT; n8++) {
                int c = n8 * 8 + cpair;
                if (row0 < N_NODES) *(float2*)(OUT + (size_t)row0 * NOUT + c) = make_float2(acc[t][n8][0], acc[t][n8][1]);
                if (row1 < N_NODES) *(float2*)(OUT + (size_t)row1 * NOUT + c) = make_float2(acc[t][n8][2], acc[t][n8][3]);
            }
        }
        return;
    }

    // ---- chained next-layer GEMM1: y_next = a @ W1next (fp32 out) ----
    __syncthreads();
#pragma unroll
    for (int t = 0; t < 2; t++) {
        int rl0 = warp * 32 + t * 16 + r_in_warp;
        int rl1 = rl0 + 8;
#pragma unroll
        for (int n8 = 0; n8 < NT; n8++) {
            int cb = (n8 * 8 + cpair) * 2;
            uint32_t h, l;
            split2(acc[t][n8][0], acc[t][n8][1], h, l);
            sts32(aHi + (uint32_t)rl0 * SPB + cb, h);
            sts32(aLo + (uint32_t)rl0 * SPB + cb, l);
            split2(acc[t][n8][2], acc[t][n8][3], h, l);
            sts32(aHi + (uint32_t)rl1 * SPB + cb, h);
            sts32(aLo + (uint32_t)rl1 * SPB + cb, l);
        }
    }
    for (int i = tid; i < 64 * K / 2; i += 128) {
        int byte = i * 4;
        int row = byte >> 7, kb = byte & 127;
        uint32_t off = (uint32_t)row * SPB + kb;
        sts32(wHi + off, ((const uint32_t*)W1hi)[i]);
        sts32(wLo + off, ((const uint32_t*)W1lo)[i]);
    }
    __syncthreads();

    float acc2[2][8][4];
#pragma unroll
    for (int t = 0; t < 2; t++)
#pragma unroll
        for (int n = 0; n < 8; n++)
#pragma unroll
            for (int j = 0; j < 4; j++) acc2[t][n][j] = 0.f;

#pragma unroll
    for (int s = 0; s < 3; s++) {
        uint32_t Ab = (s == 2) ? aLo : aHi;
        uint32_t Wb = (s == 1) ? wLo : wHi;
#pragma unroll
        for (int k16 = 0; k16 < 4; k16++) {
            uint32_t kbyte = (uint32_t)(k16 * 32);
            uint32_t af0[4], af1[4];
            ldsm4(af0, Ab + (uint32_t)arow * SPB + kbyte + ahalf * 16);
            ldsm4(af1, Ab + (uint32_t)(arow + 16) * SPB + kbyte + ahalf * 16);
#pragma unroll
            for (int n8 = 0; n8 < 8; n8++) {
                uint32_t bf[2];
                ldsm2(bf, Wb + (uint32_t)(n8 * 8 + brow) * SPB + kbyte + bhalf * 16);
                mma_bf16(acc2[0][n8], af0, bf);
                mma_bf16(acc2[1][n8], af1, bf);
            }
        }
    }
#pragma unroll
    for (int t = 0; t < 2; t++) {
        int row0 = base + warp * 32 + t * 16 + r_in_warp;
        int row1 = row0 + 8;
#pragma unroll
        for (int n8 = 0; n8 < 8; n8++) {
            int c = n8 * 8 + cpair;
            if (row0 < N_NODES) *(float2*)(OUT + (size_t)row0 * 64 + c) = make_float2(acc2[t][n8][0], acc2[t][n8][1]);
            if (row1 < N_NODES) *(float2*)(OUT + (size_t)row1 * 64 + c) = make_float2(acc2[t][n8][2], acc2[t][n8][3]);
        }
    }
}

// ================= pool =================
#define PB_NODES 64
__global__ void pool_kernel(const float* __restrict__ F, const int* __restrict__ batch,
                            float* __restrict__ sums, int* __restrict__ cnts) {
    __shared__ int sb[PB_NODES];
    const int start = blockIdx.x * PB_NODES;
    const int nn = min(PB_NODES, N_NODES - start);
    const int tid = threadIdx.x;   // 96
    if (tid < nn) sb[tid] = batch[start + tid];
    __syncthreads();
    if (tid == 0) {
        int cur = sb[0], c = 0;
        for (int n = 0; n < nn; n++) {
            int g = sb[n];
            if (g != cur) { atomicAdd(&cnts[cur], c); cur = g; c = 0; }
            c++;
        }
        atomicAdd(&cnts[cur], c);
    }
    int cur = sb[0];
    float acc = 0.f;
    for (int n = 0; n < nn; n++) {
        int g = sb[n];
        float v = F[(size_t)(start + n) * 96 + tid];
        if (g != cur) { atomicAdd(&sums[cur * 96 + tid], acc); acc = 0.f; cur = g; }
        acc += v;
    }
    atomicAdd(&sums[cur * 96 + tid], acc);
}
__global__ void finalize_kernel(const float* __restrict__ sums, const int* __restrict__ cnts,
                                float* __restrict__ out) {
    int i = blockIdx.x * blockDim.x + threadIdx.x;
    if (i >= N_GRAPHS * 96) return;
    float c = fmaxf((float)cnts[i / 96], 1.f);
    out[i] = sums[i] / c;
}

// ================= launch =================
extern "C" void kernel_launch(void* const* d_in, const int* in_sizes, int n_in,
                              void* d_out, int out_size) {
    const float* x     = (const float*)d_in[0];
    const void*  ei    = d_in[1];
    const void*  batch = d_in[2];
    const float* P[24];
    for (int i = 0; i < 24; i++) P[i] = (const float*)d_in[3 + i];

    float *y, *f, *sums;
    __nv_bfloat16 *aghi, *aglo, *whi, *wlo;
    int *cnts, *b32, *flags;
    int *deg, *rowptr, *cursor, *colv;
    unsigned long long* sstate;
    cudaGetSymbolAddress((void**)&y,      g_y);
    cudaGetSymbolAddress((void**)&aghi,   g_aghi);
    cudaGetSymbolAddress((void**)&aglo,   g_aglo);
    cudaGetSymbolAddress((void**)&f,      g_f);
    cudaGetSymbolAddress((void**)&sums,   g_sums);
    cudaGetSymbolAddress((void**)&cnts,   g_cnts);
    cudaGetSymbolAddress((void**)&b32,    g_batch32);
    cudaGetSymbolAddress((void**)&flags,  g_flags);
    cudaGetSymbolAddress((void**)&deg,    g_deg);
    cudaGetSymbolAddress((void**)&rowptr, g_rowptr);
    cudaGetSymbolAddress((void**)&cursor, g_cursor);
    cudaGetSymbolAddress((void**)&colv,   g_col);
    cudaGetSymbolAddress((void**)&sstate, g_scanstate);
    cudaGetSymbolAddress((void**)&whi,    g_whi);
    cudaGetSymbolAddress((void**)&wlo,    g_wlo);

    const int SM_L0  = (256 + 128) * (136 * 2);   // 104448
    const int SM_F64 = (256 + 128) * (72 * 2);    // 55296
    const int SM_F96 = (256 + 192) * (72 * 2);    // 64512
    cudaFuncSetAttribute((const void*)hgemm_l0, cudaFuncAttributeMaxDynamicSharedMemorySize, SM_L0);
    cudaFuncSetAttribute((const void*)fused_mlp<64, true>,  cudaFuncAttributeMaxDynamicSharedMemorySize, SM_F64);
    cudaFuncSetAttribute((const void*)fused_mlp<96, false>, cudaFuncAttributeMaxDynamicSharedMemorySize, SM_F96);

    const int NB = (N_NODES + 127) / 128;          // 782
    const int GB = (N_NODES * 32 + 255) / 256;     // 12500

    // fork-join: CSR build on stream 0, weight-split + layer-0 GEMM on s2.
    cudaStream_t s2;
    cudaStreamCreateWithFlags(&s2, cudaStreamNonBlocking);
    cudaEvent_t evFork, evJoin;
    cudaEventCreateWithFlags(&evFork, cudaEventDisableTiming);
    cudaEventCreateWithFlags(&evJoin, cudaEventDisableTiming);

    cudaEventRecord(evFork, 0);
    cudaStreamWaitEvent(s2, evFork, 0);

    // --- branch B (s2): weights + layer-0 GEMM ---
    const int O_W10 = 0, O_W20 = 8192, O_W11 = 12288, O_W21 = 16384, O_W12 = 20480, O_W22 = 24576;
    wsplit_kernel<<<WB, 256, 0, s2>>>(P[0], P[2], P[8], P[10], P[16], P[18], whi, wlo);
    hgemm_l0<<<NB, 128, SM_L0, s2>>>(x, whi + O_W10, wlo + O_W10, y);
    cudaEventRecord(evJoin, s2);

    // --- branch A (stream 0): CSR build ---
    prep_graph_kernel<<<NB_SCAN + 3, 256>>>(ei, batch, flags, deg, sums, cnts, sstate);
    convert_all_kernel<<<EB + NB_SCAN, 256>>>(ei, batch, flags, deg, b32);
    scan_onepass_kernel<<<NB_SCAN, SCAN_BS>>>(deg, rowptr, cursor, sstate);
    fill_kernel<<<EB, 256>>>(ei, flags, cursor, colv);

    // join: gather needs y (B) + rowptr/col (A)
    cudaStreamWaitEvent(0, evJoin, 0);

    gather_kernel<<<GB, 256>>>(y, rowptr, colv, P[1], aghi, aglo);
    fused_mlp<64, true><<<NB, 128, SM_F64>>>(aghi, aglo, whi + O_W20, wlo + O_W20,
                                             P[3], P[4], P[5], P[6], P[7],
                                             whi + O_W11, wlo + O_W11, y);
    gather_kernel<<<GB, 256>>>(y, rowptr, colv, P[9], aghi, aglo);
    fused_mlp<64, true><<<NB, 128, SM_F64>>>(aghi, aglo, whi + O_W21, wlo + O_W21,
                                             P[11], P[12], P[13], P[14], P[15],
                                             whi + O_W12, wlo + O_W12, y);
    gather_kernel<<<GB, 256>>>(y, rowptr, colv, P[17], aghi, aglo);
    fused_mlp<96, false><<<NB, 128, SM_F96>>>(aghi, aglo, whi + O_W22, wlo + O_W22,
                                              P[19], P[20], P[21], P[22], P[23],
                                              nullptr, nullptr, f);

    pool_kernel<<<(N_NODES + PB_NODES - 1) / PB_NODES, 96>>>(f, b32, sums, cnts);
    finalize_kernel<<<(N_GRAPHS * 96 + 255) / 256, 256>>>(sums, cnts, (float*)d_out);

    cudaEventDestroy(evFork);
    cudaEventDestroy(evJoin);
    cudaStreamDestroy(s2);
}